// round 9
// baseline (speedup 1.0000x reference)
#include <cuda_runtime.h>
#include <cuda_bf16.h>
#include <cstdint>

#define NN 50000
#define NP 50048          // padded rows (multiple of 128) for unguarded cp.async
#define EE 800000
#define HD 256
#define DESW 768

// ---------------- scratch (device globals; no runtime alloc) ----------------
__device__ __align__(16) __nv_bfloat16 g_xh[(size_t)2 * NP * HD];
__device__ __align__(16) __nv_bfloat16 g_xl[(size_t)2 * NP * HD];
__device__ __align__(16) float g_h[(size_t)3 * NN * HD];     // [rel0 | rel1 | root] fp32
__device__ __align__(16) int   g_cnt[2 * NN];
__device__ __align__(16) int   g_off[2 * NN + 1];
__device__ __align__(16) int   g_cursor[2 * NN];
__device__ __align__(16) int   g_eidx[EE];

#define OFF_DES 0
#define OFF_TW  49152
#define OFF_WIN 98304
#define OFF_R1  163840
#define OFF_R2  360448
__device__ __align__(16) __nv_bfloat16 g_whi[557056];
__device__ __align__(16) __nv_bfloat16 g_wlo[557056];

// ---------------- helpers -----------------------------------------------------
__device__ __forceinline__ uint32_t smem_u32(const void* p) {
    uint32_t a;
    asm("{ .reg .u64 t; cvta.to.shared.u64 t, %1; cvt.u32.u64 %0, t; }" : "=r"(a) : "l"(p));
    return a;
}
__device__ __forceinline__ void ldsm4(uint32_t* r, uint32_t addr) {
    asm volatile("ldmatrix.sync.aligned.m8n8.x4.shared.b16 {%0,%1,%2,%3}, [%4];"
                 : "=r"(r[0]), "=r"(r[1]), "=r"(r[2]), "=r"(r[3]) : "r"(addr));
}
__device__ __forceinline__ void mma_bf16(float* c, const uint32_t* a, const uint32_t* b) {
    asm volatile(
        "mma.sync.aligned.m16n8k16.row.col.f32.bf16.bf16.f32 "
        "{%0,%1,%2,%3}, {%4,%5,%6,%7}, {%8,%9}, {%0,%1,%2,%3};"
        : "+f"(c[0]), "+f"(c[1]), "+f"(c[2]), "+f"(c[3])
        : "r"(a[0]), "r"(a[1]), "r"(a[2]), "r"(a[3]), "r"(b[0]), "r"(b[1]));
}
__device__ __forceinline__ void cpa16(uint32_t dst, const void* src) {
    asm volatile("cp.async.cg.shared.global [%0], [%1], 16;" :: "r"(dst), "l"(src));
}
__device__ __forceinline__ void cp_commit() {
    asm volatile("cp.async.commit_group;" ::: "memory");
}
template <int N>
__device__ __forceinline__ void cp_wait() {
    asm volatile("cp.async.wait_group %0;" :: "n"(N) : "memory");
}
__device__ __forceinline__ float actf(float v, int act) {
    if (act == 1) return v > 0.f ? v : 0.01f * v;
    if (act == 2) return v > 0.f ? v : 0.f;
    return v;
}
__device__ __forceinline__ void pack_hilo(float a, float b, uint32_t& hw, uint32_t& lw) {
    __nv_bfloat16 h0 = __float2bfloat16_rn(a), h1 = __float2bfloat16_rn(b);
    float l0 = a - __bfloat162float(h0), l1 = b - __bfloat162float(h1);
    hw = (uint32_t)__bfloat16_as_ushort(h0) | ((uint32_t)__bfloat16_as_ushort(h1) << 16);
    lw = (uint32_t)__bfloat16_as_ushort(__float2bfloat16_rn(l0)) |
         ((uint32_t)__bfloat16_as_ushort(__float2bfloat16_rn(l1)) << 16);
}
__device__ __forceinline__ void cvt8(float4 x, float4 y, uint4& h, uint4& l) {
    float v[8] = {x.x, x.y, x.z, x.w, y.x, y.y, y.z, y.w};
    uint32_t hb[8], lb[8];
#pragma unroll
    for (int i = 0; i < 8; i++) {
        __nv_bfloat16 hh = __float2bfloat16_rn(v[i]);
        hb[i] = (uint32_t)__bfloat16_as_ushort(hh);
        float r = v[i] - __bfloat162float(hh);
        lb[i] = (uint32_t)__bfloat16_as_ushort(__float2bfloat16_rn(r));
    }
    h.x = hb[0] | (hb[1] << 16); h.y = hb[2] | (hb[3] << 16);
    h.z = hb[4] | (hb[5] << 16); h.w = hb[6] | (hb[7] << 16);
    l.x = lb[0] | (lb[1] << 16); l.y = lb[2] | (lb[3] << 16);
    l.z = lb[4] | (lb[5] << 16); l.w = lb[6] | (lb[7] << 16);
}

// ---------------- weight prep -------------------------------------------------
__device__ __forceinline__ void wprep_one(const float* W, int K, int N, int outOff, int id) {
    int k = id / N, n = id - k * N;
    float w = W[id];
    __nv_bfloat16 h = __float2bfloat16_rn(w);
    float lo = w - __bfloat162float(h);
    g_whi[(size_t)outOff + (size_t)n * K + k] = h;
    g_wlo[(size_t)outOff + (size_t)n * K + k] = __float2bfloat16_rn(lo);
}
__global__ void k_wprep768(const float* __restrict__ W, int outOff) {
    int id = blockIdx.x * blockDim.x + threadIdx.x;
    if (id < 768 * 64) wprep_one(W, 768, 64, outOff, id);
}
__global__ void k_wprep_all(const float* __restrict__ w_in, const float* __restrict__ wt1,
                            const float* __restrict__ rt1, const float* __restrict__ wt2,
                            const float* __restrict__ rt2) {
    int id = blockIdx.x * blockDim.x + threadIdx.x;
    if (id >= 256 * 256) return;
    int y = blockIdx.y;
    const float* W;
    int off;
    switch (y) {
        case 0: W = w_in;          off = OFF_WIN;           break;
        case 1: W = wt1;           off = OFF_R1;            break;
        case 2: W = wt1 + 65536;   off = OFF_R1 + 65536;    break;
        case 3: W = rt1;           off = OFF_R1 + 131072;   break;
        case 4: W = wt2;           off = OFF_R2;            break;
        case 5: W = wt2 + 65536;   off = OFF_R2 + 65536;    break;
        default: W = rt2;          off = OFF_R2 + 131072;   break;
    }
    wprep_one(W, 256, 256, off, id);
}

// ---------------- cp.async double-buffered bf16-split GEMM (R8 winner) --------
template <int BN, int AMODE>
__global__ void __launch_bounds__(256) k_gemm_mma(
    const float* __restrict__ Aparam, int aSlot, int K, int M, int bOff,
    const float* __restrict__ bias, int cSel, int cbase, int cmode, int act)
{
    extern __shared__ char sm[];
    constexpr int STR = 144;
    constexpr int ABUF = 128 * STR;
    constexpr int BBUF = BN * STR;
    constexpr int NT = BN / 16;

    const uint32_t smb = smem_u32(sm);
    const int tid = threadIdx.x;
    const int lane = tid & 31, wid = tid >> 5;
    const int m_base = (wid & 3) * 32;
    const int n_base = (wid >> 2) * (BN / 2);

    const __nv_bfloat16* Ah = g_xh + (size_t)aSlot * NP * HD;
    const __nv_bfloat16* Al = g_xl + (size_t)aSlot * NP * HD;
    const __nv_bfloat16* Bhi = g_whi + bOff;
    const __nv_bfloat16* Blo = g_wlo + bOff;

    const int m0 = blockIdx.y * 128;
    const int n0 = blockIdx.x * BN;
    const int nch = K >> 6;

    const int lrow = tid >> 1, lhalf = tid & 1;

    float acc[2][NT][4];
#pragma unroll
    for (int i = 0; i < 2; i++)
#pragma unroll
        for (int j = 0; j < NT; j++)
#pragma unroll
            for (int q = 0; q < 4; q++) acc[i][j][q] = 0.f;

    const uint32_t aoff = (uint32_t)(m_base + (lane & 15)) * STR + (uint32_t)(lane >> 4) * 16;
    const uint32_t boff = (uint32_t)(n_base + ((lane >> 4) & 1) * 8 + (lane & 7)) * STR +
                          (uint32_t)((lane >> 3) & 1) * 16;

    auto loadA = [&](int c, int buf) {
        if (AMODE == 1) {
            int k0 = c * 64;
            size_t base = (size_t)(m0 + lrow) * HD + k0 + lhalf * 32;
            uint32_t d = smb + buf * ABUF + lrow * STR + lhalf * 64;
            uint32_t d2 = d + 2 * ABUF;
#pragma unroll
            for (int j = 0; j < 4; j++) {
                cpa16(d + j * 16, Ah + base + j * 8);
                cpa16(d2 + j * 16, Al + base + j * 8);
            }
        }
    };
    auto loadB = [&](int c, int buf) {
        if (lrow < BN) {
            int k0 = c * 64;
            size_t base = (size_t)(n0 + lrow) * K + k0 + lhalf * 32;
            uint32_t d = smb + 4 * ABUF + buf * BBUF + lrow * STR + lhalf * 64;
            uint32_t d2 = d + 2 * BBUF;
#pragma unroll
            for (int j = 0; j < 4; j++) {
                cpa16(d + j * 16, Bhi + base + j * 8);
                cpa16(d2 + j * 16, Blo + base + j * 8);
            }
        }
    };

    loadA(0, 0);
    loadB(0, 0);
    cp_commit();

    for (int c = 0; c < nch; c++) {
        const int buf = c & 1;
        if (c + 1 < nch) {
            loadA(c + 1, buf ^ 1);
            loadB(c + 1, buf ^ 1);
            cp_commit();
            cp_wait<1>();
        } else {
            cp_wait<0>();
        }
        __syncthreads();

        if (AMODE == 0) {
            int gr = m0 + lrow;
            int k0 = c * 64;
            uint4 h[4], l[4];
            if (gr < M) {
                const float4* srcp = (const float4*)(Aparam + (size_t)gr * K + k0 + lhalf * 32);
#pragma unroll
                for (int j = 0; j < 4; j++) cvt8(srcp[2 * j], srcp[2 * j + 1], h[j], l[j]);
            } else {
#pragma unroll
                for (int j = 0; j < 4; j++) { h[j] = make_uint4(0,0,0,0); l[j] = make_uint4(0,0,0,0); }
            }
#pragma unroll
            for (int j = 0; j < 4; j++) {
                uint32_t off = buf * ABUF + lrow * STR + lhalf * 64 + j * 16;
                *(uint4*)(sm + off) = h[j];
                *(uint4*)(sm + 2 * ABUF + off) = l[j];
            }
            __syncthreads();
        }

        const uint32_t abH = smb + buf * ABUF;
        const uint32_t abL = abH + 2 * ABUF;
        const uint32_t bbH = smb + 4 * ABUF + buf * BBUF;
        const uint32_t bbL = bbH + 2 * BBUF;

#pragma unroll
        for (int k16 = 0; k16 < 4; k16++) {
            uint32_t aH[2][4], aL[2][4];
#pragma unroll
            for (int mi = 0; mi < 2; mi++) {
                uint32_t ad = aoff + mi * (16 * STR) + k16 * 32;
                ldsm4(aH[mi], abH + ad);
                ldsm4(aL[mi], abL + ad);
            }
#pragma unroll
            for (int pr = 0; pr < NT / 2; pr++) {
                uint32_t bH[4], bL[4];
                uint32_t bd = boff + pr * (16 * STR) + k16 * 32;
                ldsm4(bH, bbH + bd);
                ldsm4(bL, bbL + bd);
#pragma unroll
                for (int mi = 0; mi < 2; mi++)
#pragma unroll
                    for (int t = 0; t < 2; t++) {
                        int nt = pr * 2 + t;
                        mma_bf16(acc[mi][nt], aH[mi], bH + 2 * t);
                        mma_bf16(acc[mi][nt], aH[mi], bL + 2 * t);
                        mma_bf16(acc[mi][nt], aL[mi], bH + 2 * t);
                    }
            }
        }
        __syncthreads();
    }

#pragma unroll
    for (int mi = 0; mi < 2; mi++) {
#pragma unroll
        for (int nt = 0; nt < NT; nt++) {
            int colL = n_base + nt * 8 + (lane & 3) * 2;
            int gcolL = n0 + colL;
            int bidx = (cmode == 1) ? (gcolL & 255) : (cbase + gcolL);
            float b0 = bias[bidx], b1 = bias[bidx + 1];
#pragma unroll
            for (int half = 0; half < 2; half++) {
                int gr = m0 + m_base + mi * 16 + (lane >> 2) + half * 8;
                if (gr < M) {
                    float vx = actf(acc[mi][nt][half * 2 + 0] + b0, act);
                    float vy = actf(acc[mi][nt][half * 2 + 1] + b1, act);
                    if (cmode == 1) {
                        int seg = gcolL >> 8, lc = gcolL & 255;
                        float* cp = g_h + ((size_t)seg * M + gr) * 256 + lc;
                        *(float2*)cp = make_float2(vx, vy);
                    } else {
                        int slot = cSel - 1;
                        size_t eoff = (size_t)slot * NP * HD + (size_t)gr * HD + cbase + gcolL;
                        uint32_t hw, lw;
                        pack_hilo(vx, vy, hw, lw);
                        *(uint32_t*)(g_xh + eoff) = hw;
                        *(uint32_t*)(g_xl + eoff) = lw;
                    }
                }
            }
        }
    }
}

// ---------------- small projection (K=5/3) -> slot0 bf16 hi/lo ---------------
__global__ void k_projsmall(const float* __restrict__ A, int K,
                            const float* __restrict__ W,
                            const float* __restrict__ bias, int coloff)
{
    int id = blockIdx.x * blockDim.x + threadIdx.x;
    if (id >= NN * 64) return;
    int n = id >> 6, j = id & 63;
    float s = bias[j];
    for (int k = 0; k < K; k++) s += A[(size_t)n * K + k] * W[k * 64 + j];
    s = actf(s, 1);
    __nv_bfloat16 h = __float2bfloat16_rn(s);
    float lo = s - __bfloat162float(h);
    size_t eoff = (size_t)n * HD + coloff + j;
    g_xh[eoff] = h;
    g_xl[eoff] = __float2bfloat16_rn(lo);
}

// ---------------- CSR build ---------------------------------------------------
__global__ void k_zero_cnt() {
    int id = blockIdx.x * blockDim.x + threadIdx.x;
    if (id < 2 * NN) g_cnt[id] = 0;
}
__global__ void k_count(const int* __restrict__ dst, const int* __restrict__ et) {
    int e = blockIdx.x * blockDim.x + threadIdx.x;
    if (e >= EE) return;
    atomicAdd(&g_cnt[et[e] * NN + dst[e]], 1);
}
__global__ void k_scan() {
    __shared__ int part[1024];
    const int T = 1024;
    const int CH = (2 * NN + T - 1) / T;
    int t = threadIdx.x;
    int base = t * CH;
    int s = 0;
    for (int i = 0; i < CH; i++) {
        int idx = base + i;
        if (idx < 2 * NN) s += g_cnt[idx];
    }
    part[t] = s;
    __syncthreads();
    for (int off = 1; off < T; off <<= 1) {
        int v = (t >= off) ? part[t - off] : 0;
        __syncthreads();
        part[t] += v;
        __syncthreads();
    }
    int run = (t == 0) ? 0 : part[t - 1];
    for (int i = 0; i < CH; i++) {
        int idx = base + i;
        if (idx < 2 * NN) {
            g_off[idx] = run;
            g_cursor[idx] = run;
            run += g_cnt[idx];
        }
    }
    if (t == T - 1) g_off[2 * NN] = run;
}
__global__ void k_fill(const int* __restrict__ src, const int* __restrict__ dst,
                       const int* __restrict__ et) {
    int e = blockIdx.x * blockDim.x + threadIdx.x;
    if (e >= EE) return;
    int seg = et[e] * NN + dst[e];
    int pos = atomicAdd(&g_cursor[seg], 1);
    g_eidx[pos] = src[e];
}

// ---------------- fused gather-aggregate, 2 warps per node --------------------
// warp = (node, half): half handles 128 dims (1 float4 per lane). Edge loop
// unrolled x2 for MLP. FINAL=1: head logits via smem cross-warp combine.
template <int FINAL>
__global__ void __launch_bounds__(256) k_aggregate(int outSlot,
                                                   const float* __restrict__ Wout,
                                                   const float* __restrict__ bout,
                                                   float* __restrict__ out)
{
    __shared__ float ps0[8], ps1[8];
    int gwh = (blockIdx.x * blockDim.x + threadIdx.x) >> 5;   // node*2 + half
    int node = gwh >> 1, half = gwh & 1;
    int lane = threadIdx.x & 31;
    int wInB = threadIdx.x >> 5;
    bool active = (node < NN);

    float4 a = make_float4(0.f, 0.f, 0.f, 0.f);
    if (active) {
        const float4* rootp = (const float4*)(g_h + ((size_t)2 * NN + node) * HD) + half * 32;
        a = rootp[lane];

#pragma unroll
        for (int rel = 0; rel < 2; rel++) {
            int s0 = g_off[rel * NN + node];
            int s1 = g_off[rel * NN + node + 1];
            float4 t = make_float4(0.f, 0.f, 0.f, 0.f);
            const float* hb = g_h + (size_t)rel * NN * HD;
            int i = s0;
            for (; i + 1 < s1; i += 2) {
                int sn0 = g_eidx[i], sn1 = g_eidx[i + 1];
                const float4* r0 = (const float4*)(hb + (size_t)sn0 * HD) + half * 32;
                const float4* r1 = (const float4*)(hb + (size_t)sn1 * HD) + half * 32;
                float4 v0 = r0[lane];
                float4 v1 = r1[lane];
                t.x += v0.x; t.y += v0.y; t.z += v0.z; t.w += v0.w;
                t.x += v1.x; t.y += v1.y; t.z += v1.z; t.w += v1.w;
            }
            if (i < s1) {
                int sn = g_eidx[i];
                const float4* rp = (const float4*)(hb + (size_t)sn * HD) + half * 32;
                float4 v = rp[lane];
                t.x += v.x; t.y += v.y; t.z += v.z; t.w += v.w;
            }
            int deg = s1 - s0;
            float inv = 1.f / (float)(deg > 0 ? deg : 1);
            a.x += t.x * inv; a.y += t.y * inv; a.z += t.z * inv; a.w += t.w * inv;
        }
    }

    if (FINAL == 0) {
        if (active) {
            size_t eoff = (size_t)outSlot * NP * HD + (size_t)node * HD + half * 128 + lane * 4;
            uint32_t h0, l0, h1, l1;
            pack_hilo(a.x, a.y, h0, l0);
            pack_hilo(a.z, a.w, h1, l1);
            *(uint2*)(g_xh + eoff) = make_uint2(h0, h1);
            *(uint2*)(g_xl + eoff) = make_uint2(l0, l1);
        }
    } else {
        // head: partial dot over this warp's 128 dims, combine across warp pair
        float s0 = 0.f, s1 = 0.f;
        if (active) {
            float va[4] = {a.x, a.y, a.z, a.w};
            int c0 = half * 128 + lane * 4;
#pragma unroll
            for (int q = 0; q < 4; q++) {
                float2 w = *(const float2*)(Wout + (c0 + q) * 2);
                s0 += va[q] * w.x;
                s1 += va[q] * w.y;
            }
        }
#pragma unroll
        for (int o = 16; o; o >>= 1) {
            s0 += __shfl_down_sync(0xFFFFFFFFu, s0, o);
            s1 += __shfl_down_sync(0xFFFFFFFFu, s1, o);
        }
        if (lane == 0) { ps0[wInB] = s0; ps1[wInB] = s1; }
        __syncthreads();
        if (active && half == 0 && lane == 0) {
            out[(size_t)node * 2 + 0] = ps0[wInB] + ps0[wInB + 1] + bout[0];
            out[(size_t)node * 2 + 1] = ps1[wInB] + ps1[wInB + 1] + bout[1];
        }
    }
}

// ---------------- launch ------------------------------------------------------
extern "C" void kernel_launch(void* const* d_in, const int* in_sizes, int n_in,
                              void* d_out, int out_size)
{
    const float* des   = (const float*)d_in[0];
    const float* tweet = (const float*)d_in[1];
    const float* nump  = (const float*)d_in[2];
    const float* catp  = (const float*)d_in[3];
    const int*   ei    = (const int*)d_in[4];
    const int*   et    = (const int*)d_in[5];
    const float* w_des = (const float*)d_in[6];
    const float* b_des = (const float*)d_in[7];
    const float* w_tw  = (const float*)d_in[8];
    const float* b_tw  = (const float*)d_in[9];
    const float* w_num = (const float*)d_in[10];
    const float* b_num = (const float*)d_in[11];
    const float* w_cat = (const float*)d_in[12];
    const float* b_cat = (const float*)d_in[13];
    const float* w_in  = (const float*)d_in[14];
    const float* b_in  = (const float*)d_in[15];
    const float* wt1   = (const float*)d_in[16];
    const float* rt1   = (const float*)d_in[17];
    const float* bs1   = (const float*)d_in[18];
    const float* wt2   = (const float*)d_in[19];
    const float* rt2   = (const float*)d_in[20];
    const float* bs2   = (const float*)d_in[21];
    const float* w_out = (const float*)d_in[22];
    const float* b_out = (const float*)d_in[23];
    float* out = (float*)d_out;

    const int* src = ei;
    const int* dst = ei + EE;

    const int SZ128 = 4 * 18432 + 4 * 128 * 144;    // 147456
    const int SZ64  = 4 * 18432 + 4 * 64 * 144;     // 110592
    cudaFuncSetAttribute(k_gemm_mma<128, 1>, cudaFuncAttributeMaxDynamicSharedMemorySize, SZ128);
    cudaFuncSetAttribute(k_gemm_mma<64, 0>,  cudaFuncAttributeMaxDynamicSharedMemorySize, SZ64);

    // weight prep
    k_wprep768<<<(768 * 64 + 255) / 256, 256>>>(w_des, OFF_DES);
    k_wprep768<<<(768 * 64 + 255) / 256, 256>>>(w_tw, OFF_TW);
    k_wprep_all<<<dim3((256 * 256 + 255) / 256, 7), 256>>>(w_in, wt1, rt1, wt2, rt2);

    // CSR build
    k_zero_cnt<<<(2 * NN + 255) / 256, 256>>>();
    k_count<<<(EE + 255) / 256, 256>>>(dst, et);
    k_scan<<<1, 1024>>>();
    k_fill<<<(EE + 255) / 256, 256>>>(src, dst, et);

    const int MB = (NN + 127) / 128;  // 391 row tiles

    // feature projections -> slot0
    k_gemm_mma<64, 0><<<dim3(1, MB), 256, SZ64>>>(des, 0, 768, NN, OFF_DES, b_des, 1, 0, 0, 1);
    k_gemm_mma<64, 0><<<dim3(1, MB), 256, SZ64>>>(tweet, 0, 768, NN, OFF_TW, b_tw, 1, 64, 0, 1);
    {
        int th = NN * 64, bl = (th + 255) / 256;
        k_projsmall<<<bl, 256>>>(nump, 5, w_num, b_num, 128);
        k_projsmall<<<bl, 256>>>(catp, 3, w_cat, b_cat, 192);
    }

    // x = lrelu(slot0 @ w_in + b_in) -> slot1
    k_gemm_mma<128, 1><<<dim3(2, MB), 256, SZ128>>>(nullptr, 0, 256, NN, OFF_WIN, b_in, 2, 0, 0, 1);

    const int agBl = (NN * 2 * 32 + 255) / 256;   // 12500, exact

    // RGCN layer 1: slot1 -> g_h -> slot0
    k_gemm_mma<128, 1><<<dim3(6, MB), 256, SZ128>>>(nullptr, 1, 256, NN, OFF_R1, bs1, 3, 0, 1, 2);
    k_aggregate<0><<<agBl, 256>>>(0, nullptr, nullptr, nullptr);

    // RGCN layer 2: slot0 -> g_h -> head logits (fused)
    k_gemm_mma<128, 1><<<dim3(6, MB), 256, SZ128>>>(nullptr, 0, 256, NN, OFF_R2, bs2, 3, 0, 1, 2);
    k_aggregate<1><<<agBl, 256>>>(0, w_out, b_out, out);
}

// round 11
// speedup vs baseline: 1.1074x; 1.1074x over previous
#include <cuda_runtime.h>
#include <cuda_bf16.h>
#include <cuda_fp16.h>
#include <cstdint>

#define NN 50000
#define NP 50048          // padded rows (multiple of 128) for unguarded cp.async
#define EE 800000
#define HD 256
#define DESW 768

// ---------------- scratch (device globals; no runtime alloc) ----------------
__device__ __align__(16) __nv_bfloat16 g_xh[(size_t)2 * NP * HD];
__device__ __align__(16) __nv_bfloat16 g_xl[(size_t)2 * NP * HD];
__device__ __align__(16) __half g_hrel[(size_t)2 * NN * HD];   // fp16 messages
__device__ __align__(16) float  g_hroot[(size_t)NN * HD];      // fp32 root
__device__ __align__(16) int   g_cnt[2 * NN];
__device__ __align__(16) int   g_off[2 * NN + 1];
__device__ __align__(16) int   g_cursor[2 * NN];
__device__ __align__(16) int   g_eidx[EE];

#define OFF_DES 0
#define OFF_TW  49152
#define OFF_WIN 98304
#define OFF_R1  163840
#define OFF_R2  360448
__device__ __align__(16) __nv_bfloat16 g_whi[557056];
__device__ __align__(16) __nv_bfloat16 g_wlo[557056];

// ---------------- helpers -----------------------------------------------------
__device__ __forceinline__ uint32_t smem_u32(const void* p) {
    uint32_t a;
    asm("{ .reg .u64 t; cvta.to.shared.u64 t, %1; cvt.u32.u64 %0, t; }" : "=r"(a) : "l"(p));
    return a;
}
__device__ __forceinline__ void ldsm4(uint32_t* r, uint32_t addr) {
    asm volatile("ldmatrix.sync.aligned.m8n8.x4.shared.b16 {%0,%1,%2,%3}, [%4];"
                 : "=r"(r[0]), "=r"(r[1]), "=r"(r[2]), "=r"(r[3]) : "r"(addr));
}
__device__ __forceinline__ void mma_bf16(float* c, const uint32_t* a, const uint32_t* b) {
    asm volatile(
        "mma.sync.aligned.m16n8k16.row.col.f32.bf16.bf16.f32 "
        "{%0,%1,%2,%3}, {%4,%5,%6,%7}, {%8,%9}, {%0,%1,%2,%3};"
        : "+f"(c[0]), "+f"(c[1]), "+f"(c[2]), "+f"(c[3])
        : "r"(a[0]), "r"(a[1]), "r"(a[2]), "r"(a[3]), "r"(b[0]), "r"(b[1]));
}
__device__ __forceinline__ void cpa16(uint32_t dst, const void* src) {
    asm volatile("cp.async.cg.shared.global [%0], [%1], 16;" :: "r"(dst), "l"(src));
}
__device__ __forceinline__ void cp_commit() {
    asm volatile("cp.async.commit_group;" ::: "memory");
}
template <int N>
__device__ __forceinline__ void cp_wait() {
    asm volatile("cp.async.wait_group %0;" :: "n"(N) : "memory");
}
__device__ __forceinline__ float actf(float v, int act) {
    if (act == 1) return v > 0.f ? v : 0.01f * v;
    if (act == 2) return v > 0.f ? v : 0.f;
    return v;
}
__device__ __forceinline__ void pack_hilo(float a, float b, uint32_t& hw, uint32_t& lw) {
    __nv_bfloat16 h0 = __float2bfloat16_rn(a), h1 = __float2bfloat16_rn(b);
    float l0 = a - __bfloat162float(h0), l1 = b - __bfloat162float(h1);
    hw = (uint32_t)__bfloat16_as_ushort(h0) | ((uint32_t)__bfloat16_as_ushort(h1) << 16);
    lw = (uint32_t)__bfloat16_as_ushort(__float2bfloat16_rn(l0)) |
         ((uint32_t)__bfloat16_as_ushort(__float2bfloat16_rn(l1)) << 16);
}
__device__ __forceinline__ void cvt8(float4 x, float4 y, uint4& h, uint4& l) {
    float v[8] = {x.x, x.y, x.z, x.w, y.x, y.y, y.z, y.w};
    uint32_t hb[8], lb[8];
#pragma unroll
    for (int i = 0; i < 8; i++) {
        __nv_bfloat16 hh = __float2bfloat16_rn(v[i]);
        hb[i] = (uint32_t)__bfloat16_as_ushort(hh);
        float r = v[i] - __bfloat162float(hh);
        lb[i] = (uint32_t)__bfloat16_as_ushort(__float2bfloat16_rn(r));
    }
    h.x = hb[0] | (hb[1] << 16); h.y = hb[2] | (hb[3] << 16);
    h.z = hb[4] | (hb[5] << 16); h.w = hb[6] | (hb[7] << 16);
    l.x = lb[0] | (lb[1] << 16); l.y = lb[2] | (lb[3] << 16);
    l.z = lb[4] | (lb[5] << 16); l.w = lb[6] | (lb[7] << 16);
}

// ---------------- weight prep -------------------------------------------------
__device__ __forceinline__ void wprep_one(const float* W, int K, int N, int outOff, int id) {
    int k = id / N, n = id - k * N;
    float w = W[id];
    __nv_bfloat16 h = __float2bfloat16_rn(w);
    float lo = w - __bfloat162float(h);
    g_whi[(size_t)outOff + (size_t)n * K + k] = h;
    g_wlo[(size_t)outOff + (size_t)n * K + k] = __float2bfloat16_rn(lo);
}
__global__ void k_wprep768(const float* __restrict__ Wd, const float* __restrict__ Wt) {
    int id = blockIdx.x * blockDim.x + threadIdx.x;
    if (id >= 768 * 64) return;
    wprep_one(blockIdx.y ? Wt : Wd, 768, 64, blockIdx.y ? OFF_TW : OFF_DES, id);
}
__global__ void k_wprep_all(const float* __restrict__ w_in, const float* __restrict__ wt1,
                            const float* __restrict__ rt1, const float* __restrict__ wt2,
                            const float* __restrict__ rt2) {
    int id = blockIdx.x * blockDim.x + threadIdx.x;
    if (id >= 256 * 256) return;
    int y = blockIdx.y;
    const float* W;
    int off;
    switch (y) {
        case 0: W = w_in;          off = OFF_WIN;           break;
        case 1: W = wt1;           off = OFF_R1;            break;
        case 2: W = wt1 + 65536;   off = OFF_R1 + 65536;    break;
        case 3: W = rt1;           off = OFF_R1 + 131072;   break;
        case 4: W = wt2;           off = OFF_R2;            break;
        case 5: W = wt2 + 65536;   off = OFF_R2 + 65536;    break;
        default: W = rt2;          off = OFF_R2 + 131072;   break;
    }
    wprep_one(W, 256, 256, off, id);
}

// ---------------- cp.async double-buffered bf16-split GEMM --------------------
// AMODE 0: A = external fp32 (des/tweet merged: blockIdx.x selects), writes slot0.
// AMODE 1: A = bf16 hi/lo slot (cp.async).
// cmode 0: writes bf16 hi/lo x slot; cmode 1: rel segs -> g_hrel fp16, root -> g_hroot fp32.
template <int BN, int AMODE>
__global__ void __launch_bounds__(256) k_gemm_mma(
    const float* __restrict__ Ap0, const float* __restrict__ Ap1, int aSlot,
    int K, int M, int bOff,
    const float* __restrict__ bias0, const float* __restrict__ bias1,
    int cSel, int cbase, int cmode, int act)
{
    extern __shared__ char sm[];
    constexpr int STR = 144;
    constexpr int ABUF = 128 * STR;
    constexpr int BBUF = BN * STR;
    constexpr int NT = BN / 16;

    const uint32_t smb = smem_u32(sm);
    const int tid = threadIdx.x;
    const int lane = tid & 31, wid = tid >> 5;
    const int m_base = (wid & 3) * 32;
    const int n_base = (wid >> 2) * (BN / 2);

    const float* Aparam = (AMODE == 0 && blockIdx.x) ? Ap1 : Ap0;
    const float* bias = (AMODE == 0 && blockIdx.x) ? bias1 : bias0;
    const int cb = (AMODE == 0) ? (blockIdx.x ? cbase : 0) : cbase;
    const int boff_g = (AMODE == 0) ? (blockIdx.x ? OFF_TW : OFF_DES) : bOff;

    const __nv_bfloat16* Ah = g_xh + (size_t)aSlot * NP * HD;
    const __nv_bfloat16* Al = g_xl + (size_t)aSlot * NP * HD;
    const __nv_bfloat16* Bhi = g_whi + boff_g;
    const __nv_bfloat16* Blo = g_wlo + boff_g;

    const int m0 = blockIdx.y * 128;
    const int n0 = (AMODE == 0) ? 0 : blockIdx.x * BN;
    const int nch = K >> 6;

    const int lrow = tid >> 1, lhalf = tid & 1;

    float acc[2][NT][4];
#pragma unroll
    for (int i = 0; i < 2; i++)
#pragma unroll
        for (int j = 0; j < NT; j++)
#pragma unroll
            for (int q = 0; q < 4; q++) acc[i][j][q] = 0.f;

    const uint32_t aoff = (uint32_t)(m_base + (lane & 15)) * STR + (uint32_t)(lane >> 4) * 16;
    const uint32_t boff = (uint32_t)(n_base + ((lane >> 4) & 1) * 8 + (lane & 7)) * STR +
                          (uint32_t)((lane >> 3) & 1) * 16;

    auto loadA = [&](int c, int buf) {
        if (AMODE == 1) {
            int k0 = c * 64;
            size_t base = (size_t)(m0 + lrow) * HD + k0 + lhalf * 32;
            uint32_t d = smb + buf * ABUF + lrow * STR + lhalf * 64;
            uint32_t d2 = d + 2 * ABUF;
#pragma unroll
            for (int j = 0; j < 4; j++) {
                cpa16(d + j * 16, Ah + base + j * 8);
                cpa16(d2 + j * 16, Al + base + j * 8);
            }
        }
    };
    auto loadB = [&](int c, int buf) {
        if (lrow < BN) {
            int k0 = c * 64;
            size_t base = (size_t)(n0 + lrow) * K + k0 + lhalf * 32;
            uint32_t d = smb + 4 * ABUF + buf * BBUF + lrow * STR + lhalf * 64;
            uint32_t d2 = d + 2 * BBUF;
#pragma unroll
            for (int j = 0; j < 4; j++) {
                cpa16(d + j * 16, Bhi + base + j * 8);
                cpa16(d2 + j * 16, Blo + base + j * 8);
            }
        }
    };

    loadA(0, 0);
    loadB(0, 0);
    cp_commit();

    for (int c = 0; c < nch; c++) {
        const int buf = c & 1;
        if (c + 1 < nch) {
            loadA(c + 1, buf ^ 1);
            loadB(c + 1, buf ^ 1);
            cp_commit();
            cp_wait<1>();
        } else {
            cp_wait<0>();
        }
        __syncthreads();

        if (AMODE == 0) {
            int gr = m0 + lrow;
            int k0 = c * 64;
            uint4 h[4], l[4];
            if (gr < M) {
                const float4* srcp = (const float4*)(Aparam + (size_t)gr * K + k0 + lhalf * 32);
#pragma unroll
                for (int j = 0; j < 4; j++) cvt8(srcp[2 * j], srcp[2 * j + 1], h[j], l[j]);
            } else {
#pragma unroll
                for (int j = 0; j < 4; j++) { h[j] = make_uint4(0,0,0,0); l[j] = make_uint4(0,0,0,0); }
            }
#pragma unroll
            for (int j = 0; j < 4; j++) {
                uint32_t off = buf * ABUF + lrow * STR + lhalf * 64 + j * 16;
                *(uint4*)(sm + off) = h[j];
                *(uint4*)(sm + 2 * ABUF + off) = l[j];
            }
            __syncthreads();
        }

        const uint32_t abH = smb + buf * ABUF;
        const uint32_t abL = abH + 2 * ABUF;
        const uint32_t bbH = smb + 4 * ABUF + buf * BBUF;
        const uint32_t bbL = bbH + 2 * BBUF;

#pragma unroll
        for (int k16 = 0; k16 < 4; k16++) {
            uint32_t aH[2][4], aL[2][4];
#pragma unroll
            for (int mi = 0; mi < 2; mi++) {
                uint32_t ad = aoff + mi * (16 * STR) + k16 * 32;
                ldsm4(aH[mi], abH + ad);
                ldsm4(aL[mi], abL + ad);
            }
#pragma unroll
            for (int pr = 0; pr < NT / 2; pr++) {
                uint32_t bH[4], bL[4];
                uint32_t bd = boff + pr * (16 * STR) + k16 * 32;
                ldsm4(bH, bbH + bd);
                ldsm4(bL, bbL + bd);
#pragma unroll
                for (int mi = 0; mi < 2; mi++)
#pragma unroll
                    for (int t = 0; t < 2; t++) {
                        int nt = pr * 2 + t;
                        mma_bf16(acc[mi][nt], aH[mi], bH + 2 * t);
                        mma_bf16(acc[mi][nt], aH[mi], bL + 2 * t);
                        mma_bf16(acc[mi][nt], aL[mi], bH + 2 * t);
                    }
            }
        }
        __syncthreads();
    }

    // ---- epilogue ----
#pragma unroll
    for (int mi = 0; mi < 2; mi++) {
#pragma unroll
        for (int nt = 0; nt < NT; nt++) {
            int colL = n_base + nt * 8 + (lane & 3) * 2;
            int gcolL = n0 + colL;
            int bidx = (cmode == 1) ? (gcolL & 255) : colL;
            float b0 = bias[bidx], b1 = bias[bidx + 1];
#pragma unroll
            for (int half = 0; half < 2; half++) {
                int gr = m0 + m_base + mi * 16 + (lane >> 2) + half * 8;
                if (gr < M) {
                    float vx = actf(acc[mi][nt][half * 2 + 0] + b0, act);
                    float vy = actf(acc[mi][nt][half * 2 + 1] + b1, act);
                    if (cmode == 1) {
                        int seg = gcolL >> 8, lc = gcolL & 255;
                        if (seg < 2) {
                            __half2 hv = __floats2half2_rn(vx, vy);
                            *(__half2*)(g_hrel + ((size_t)seg * NN + gr) * 256 + lc) = hv;
                        } else {
                            *(float2*)(g_hroot + (size_t)gr * 256 + lc) = make_float2(vx, vy);
                        }
                    } else {
                        int slot = cSel - 1;
                        size_t eoff = (size_t)slot * NP * HD + (size_t)gr * HD + cb + gcolL;
                        uint32_t hw, lw;
                        pack_hilo(vx, vy, hw, lw);
                        *(uint32_t*)(g_xh + eoff) = hw;
                        *(uint32_t*)(g_xl + eoff) = lw;
                    }
                }
            }
        }
    }
}

// ---------------- small projection (K=5/3) -> slot0 bf16 hi/lo ---------------
__global__ void k_projsmall(const float* __restrict__ A, int K,
                            const float* __restrict__ W,
                            const float* __restrict__ bias, int coloff)
{
    int id = blockIdx.x * blockDim.x + threadIdx.x;
    if (id >= NN * 64) return;
    int n = id >> 6, j = id & 63;
    float s = bias[j];
    for (int k = 0; k < K; k++) s += A[(size_t)n * K + k] * W[k * 64 + j];
    s = actf(s, 1);
    __nv_bfloat16 h = __float2bfloat16_rn(s);
    float lo = s - __bfloat162float(h);
    size_t eoff = (size_t)n * HD + coloff + j;
    g_xh[eoff] = h;
    g_xl[eoff] = __float2bfloat16_rn(lo);
}

// ---------------- CSR build ---------------------------------------------------
__global__ void k_zero_cnt() {
    int id = blockIdx.x * blockDim.x + threadIdx.x;
    if (id < 2 * NN) g_cnt[id] = 0;
}
__global__ void k_count(const int* __restrict__ dst, const int* __restrict__ et) {
    int e = blockIdx.x * blockDim.x + threadIdx.x;
    if (e >= EE) return;
    atomicAdd(&g_cnt[et[e] * NN + dst[e]], 1);
}
__global__ void k_scan() {
    __shared__ int part[1024];
    const int T = 1024;
    const int CH = (2 * NN + T - 1) / T;
    int t = threadIdx.x;
    int base = t * CH;
    int s = 0;
    for (int i = 0; i < CH; i++) {
        int idx = base + i;
        if (idx < 2 * NN) s += g_cnt[idx];
    }
    part[t] = s;
    __syncthreads();
    for (int off = 1; off < T; off <<= 1) {
        int v = (t >= off) ? part[t - off] : 0;
        __syncthreads();
        part[t] += v;
        __syncthreads();
    }
    int run = (t == 0) ? 0 : part[t - 1];
    for (int i = 0; i < CH; i++) {
        int idx = base + i;
        if (idx < 2 * NN) {
            g_off[idx] = run;
            g_cursor[idx] = run;
            run += g_cnt[idx];
        }
    }
    if (t == T - 1) g_off[2 * NN] = run;
}
__global__ void k_fill(const int* __restrict__ src, const int* __restrict__ dst,
                       const int* __restrict__ et) {
    int e = blockIdx.x * blockDim.x + threadIdx.x;
    if (e >= EE) return;
    int seg = et[e] * NN + dst[e];
    int pos = atomicAdd(&g_cursor[seg], 1);
    g_eidx[pos] = src[e];
}

// ---------------- fused gather-aggregate (one warp per node, fp16 messages) ---
// lane covers dims [lane*8, lane*8+8). FINAL=1: fused head logits.
template <int FINAL>
__global__ void __launch_bounds__(256) k_aggregate(int outSlot,
                                                   const float* __restrict__ Wout,
                                                   const float* __restrict__ bout,
                                                   float* __restrict__ out)
{
    int gw = (blockIdx.x * blockDim.x + threadIdx.x) >> 5;
    int lane = threadIdx.x & 31;
    if (gw >= NN) return;

    float a[8];
    {
        const float4* rootp = (const float4*)(g_hroot + (size_t)gw * HD + lane * 8);
        float4 r0 = rootp[0], r1 = rootp[1];
        a[0] = r0.x; a[1] = r0.y; a[2] = r0.z; a[3] = r0.w;
        a[4] = r1.x; a[5] = r1.y; a[6] = r1.z; a[7] = r1.w;
    }

#pragma unroll
    for (int rel = 0; rel < 2; rel++) {
        int s0 = g_off[rel * NN + gw];
        int s1 = g_off[rel * NN + gw + 1];
        float t[8];
#pragma unroll
        for (int q = 0; q < 8; q++) t[q] = 0.f;
        const __half* hb = g_hrel + (size_t)rel * NN * HD;
        int i = s0;
        for (; i + 1 < s1; i += 2) {
            int sn0 = g_eidx[i], sn1 = g_eidx[i + 1];
            uint4 w0 = *(const uint4*)(hb + (size_t)sn0 * HD + lane * 8);
            uint4 w1 = *(const uint4*)(hb + (size_t)sn1 * HD + lane * 8);
            const uint32_t* p0 = &w0.x;
            const uint32_t* p1 = &w1.x;
#pragma unroll
            for (int q = 0; q < 4; q++) {
                float2 f0 = __half22float2(*(const __half2*)&p0[q]);
                float2 f1 = __half22float2(*(const __half2*)&p1[q]);
                t[q * 2 + 0] += f0.x + f1.x;
                t[q * 2 + 1] += f0.y + f1.y;
            }
        }
        if (i < s1) {
            int sn = g_eidx[i];
            uint4 w0 = *(const uint4*)(hb + (size_t)sn * HD + lane * 8);
            const uint32_t* p0 = &w0.x;
#pragma unroll
            for (int q = 0; q < 4; q++) {
                float2 f0 = __half22float2(*(const __half2*)&p0[q]);
                t[q * 2 + 0] += f0.x;
                t[q * 2 + 1] += f0.y;
            }
        }
        int deg = s1 - s0;
        float inv = 1.f / (float)(deg > 0 ? deg : 1);
#pragma unroll
        for (int q = 0; q < 8; q++) a[q] += t[q] * inv;
    }

    if (FINAL == 0) {
        size_t eoff = (size_t)outSlot * NP * HD + (size_t)gw * HD + lane * 8;
        uint4 hv, lv;
        pack_hilo(a[0], a[1], hv.x, lv.x);
        pack_hilo(a[2], a[3], hv.y, lv.y);
        pack_hilo(a[4], a[5], hv.z, lv.z);
        pack_hilo(a[6], a[7], hv.w, lv.w);
        *(uint4*)(g_xh + eoff) = hv;
        *(uint4*)(g_xl + eoff) = lv;
    } else {
        float s0 = 0.f, s1 = 0.f;
        int c0 = lane * 8;
#pragma unroll
        for (int q = 0; q < 8; q++) {
            float2 w = *(const float2*)(Wout + (c0 + q) * 2);
            s0 += a[q] * w.x;
            s1 += a[q] * w.y;
        }
#pragma unroll
        for (int o = 16; o; o >>= 1) {
            s0 += __shfl_down_sync(0xFFFFFFFFu, s0, o);
            s1 += __shfl_down_sync(0xFFFFFFFFu, s1, o);
        }
        if (lane == 0) {
            out[(size_t)gw * 2 + 0] = s0 + bout[0];
            out[(size_t)gw * 2 + 1] = s1 + bout[1];
        }
    }
}

// ---------------- launch ------------------------------------------------------
extern "C" void kernel_launch(void* const* d_in, const int* in_sizes, int n_in,
                              void* d_out, int out_size)
{
    const float* des   = (const float*)d_in[0];
    const float* tweet = (const float*)d_in[1];
    const float* nump  = (const float*)d_in[2];
    const float* catp  = (const float*)d_in[3];
    const int*   ei    = (const int*)d_in[4];
    const int*   et    = (const int*)d_in[5];
    const float* w_des = (const float*)d_in[6];
    const float* b_des = (const float*)d_in[7];
    const float* w_tw  = (const float*)d_in[8];
    const float* b_tw  = (const float*)d_in[9];
    const float* w_num = (const float*)d_in[10];
    const float* b_num = (const float*)d_in[11];
    const float* w_cat = (const float*)d_in[12];
    const float* b_cat = (const float*)d_in[13];
    const float* w_in  = (const float*)d_in[14];
    const float* b_in  = (const float*)d_in[15];
    const float* wt1   = (const float*)d_in[16];
    const float* rt1   = (const float*)d_in[17];
    const float* bs1   = (const float*)d_in[18];
    const float* wt2   = (const float*)d_in[19];
    const float* rt2   = (const float*)d_in[20];
    const float* bs2   = (const float*)d_in[21];
    const float* w_out = (const float*)d_in[22];
    const float* b_out = (const float*)d_in[23];
    float* out = (float*)d_out;

    const int* src = ei;
    const int* dst = ei + EE;

    const int SZ128 = 4 * 18432 + 4 * 128 * 144;    // 147456
    const int SZ64  = 4 * 18432 + 4 * 64 * 144;     // 110592
    cudaFuncSetAttribute(k_gemm_mma<128, 1>, cudaFuncAttributeMaxDynamicSharedMemorySize, SZ128);
    cudaFuncSetAttribute(k_gemm_mma<64, 0>,  cudaFuncAttributeMaxDynamicSharedMemorySize, SZ64);

    // weight prep
    k_wprep768<<<dim3((768 * 64 + 255) / 256, 2), 256>>>(w_des, w_tw);
    k_wprep_all<<<dim3((256 * 256 + 255) / 256, 7), 256>>>(w_in, wt1, rt1, wt2, rt2);

    // CSR build
    k_zero_cnt<<<(2 * NN + 255) / 256, 256>>>();
    k_count<<<(EE + 255) / 256, 256>>>(dst, et);
    k_scan<<<1, 1024>>>();
    k_fill<<<(EE + 255) / 256, 256>>>(src, dst, et);

    const int MB = (NN + 127) / 128;  // 391 row tiles

    // feature projections -> slot0 (des + tweet in one launch, grid.x selects)
    k_gemm_mma<64, 0><<<dim3(2, MB), 256, SZ64>>>(des, tweet, 0, 768, NN, 0,
                                                  b_des, b_tw, 1, 64, 0, 1);
    {
        int th = NN * 64, bl = (th + 255) / 256;
        k_projsmall<<<bl, 256>>>(nump, 5, w_num, b_num, 128);
        k_projsmall<<<bl, 256>>>(catp, 3, w_cat, b_cat, 192);
    }

    // x = lrelu(slot0 @ w_in + b_in) -> slot1
    k_gemm_mma<128, 1><<<dim3(2, MB), 256, SZ128>>>(nullptr, nullptr, 0, 256, NN, OFF_WIN,
                                                    b_in, nullptr, 2, 0, 0, 1);

    const int agBl = (NN * 32 + 255) / 256;

    // RGCN layer 1: slot1 -> g_hrel/g_hroot -> slot0
    k_gemm_mma<128, 1><<<dim3(6, MB), 256, SZ128>>>(nullptr, nullptr, 1, 256, NN, OFF_R1,
                                                    bs1, nullptr, 3, 0, 1, 2);
    k_aggregate<0><<<agBl, 256>>>(0, nullptr, nullptr, nullptr);

    // RGCN layer 2: slot0 -> g_hrel/g_hroot -> head logits (fused)
    k_gemm_mma<128, 1><<<dim3(6, MB), 256, SZ128>>>(nullptr, nullptr, 0, 256, NN, OFF_R2,
                                                    bs2, nullptr, 3, 0, 1, 2);
    k_aggregate<1><<<agBl, 256>>>(0, w_out, b_out, out);
}

// round 12
// speedup vs baseline: 1.4493x; 1.3087x over previous
#include <cuda_runtime.h>
#include <cuda_bf16.h>
#include <cuda_fp16.h>
#include <cstdint>

#define NN 50000
#define NP 50048          // padded rows (multiple of 128) for unguarded cp.async
#define EE 800000
#define HD 256
#define DESW 768

// ---------------- scratch (device globals; no runtime alloc) ----------------
__device__ __align__(16) __half g_x[(size_t)2 * NP * HD];      // fp16 activations, 2 slots
__device__ __align__(16) __half g_hrel[(size_t)2 * NN * HD];   // fp16 messages
__device__ __align__(16) float  g_hroot[(size_t)NN * HD];      // fp32 root
__device__ __align__(16) int   g_cnt[2 * NN];
__device__ __align__(16) int   g_off[2 * NN + 1];
__device__ __align__(16) int   g_cursor[2 * NN];
__device__ __align__(16) int   g_eidx[EE];

#define OFF_DES 0
#define OFF_TW  49152
#define OFF_WIN 98304
#define OFF_R1  163840
#define OFF_R2  360448
__device__ __align__(16) __half g_whi[557056];   // fp16 weight hi
__device__ __align__(16) __half g_wlo[557056];   // fp16 weight lo (residual)

// ---------------- helpers -----------------------------------------------------
__device__ __forceinline__ uint32_t smem_u32(const void* p) {
    uint32_t a;
    asm("{ .reg .u64 t; cvta.to.shared.u64 t, %1; cvt.u32.u64 %0, t; }" : "=r"(a) : "l"(p));
    return a;
}
__device__ __forceinline__ void ldsm4(uint32_t* r, uint32_t addr) {
    asm volatile("ldmatrix.sync.aligned.m8n8.x4.shared.b16 {%0,%1,%2,%3}, [%4];"
                 : "=r"(r[0]), "=r"(r[1]), "=r"(r[2]), "=r"(r[3]) : "r"(addr));
}
__device__ __forceinline__ void mma_f16(float* c, const uint32_t* a, const uint32_t* b) {
    asm volatile(
        "mma.sync.aligned.m16n8k16.row.col.f32.f16.f16.f32 "
        "{%0,%1,%2,%3}, {%4,%5,%6,%7}, {%8,%9}, {%0,%1,%2,%3};"
        : "+f"(c[0]), "+f"(c[1]), "+f"(c[2]), "+f"(c[3])
        : "r"(a[0]), "r"(a[1]), "r"(a[2]), "r"(a[3]), "r"(b[0]), "r"(b[1]));
}
__device__ __forceinline__ void cpa16(uint32_t dst, const void* src) {
    asm volatile("cp.async.cg.shared.global [%0], [%1], 16;" :: "r"(dst), "l"(src));
}
__device__ __forceinline__ void cp_commit() {
    asm volatile("cp.async.commit_group;" ::: "memory");
}
template <int N>
__device__ __forceinline__ void cp_wait() {
    asm volatile("cp.async.wait_group %0;" :: "n"(N) : "memory");
}
__device__ __forceinline__ float actf(float v, int act) {
    if (act == 1) return v > 0.f ? v : 0.01f * v;
    if (act == 2) return v > 0.f ? v : 0.f;
    return v;
}
// 8 fp32 -> 8 fp16 packed in uint4
__device__ __forceinline__ uint4 cvt8h(float4 x, float4 y) {
    uint4 r;
    *(__half2*)&r.x = __floats2half2_rn(x.x, x.y);
    *(__half2*)&r.y = __floats2half2_rn(x.z, x.w);
    *(__half2*)&r.z = __floats2half2_rn(y.x, y.y);
    *(__half2*)&r.w = __floats2half2_rn(y.z, y.w);
    return r;
}

// ---------------- weight prep: W[K,N] fp32 -> fp16 hi/lo transposed ----------
__device__ __forceinline__ void wprep_one(const float* W, int K, int N, int outOff, int id) {
    int k = id / N, n = id - k * N;
    float w = W[id];
    __half h = __float2half_rn(w);
    float lo = w - __half2float(h);
    g_whi[(size_t)outOff + (size_t)n * K + k] = h;
    g_wlo[(size_t)outOff + (size_t)n * K + k] = __float2half_rn(lo);
}
__global__ void k_wprep768(const float* __restrict__ Wd, const float* __restrict__ Wt) {
    int id = blockIdx.x * blockDim.x + threadIdx.x;
    if (id >= 768 * 64) return;
    wprep_one(blockIdx.y ? Wt : Wd, 768, 64, blockIdx.y ? OFF_TW : OFF_DES, id);
}
__global__ void k_wprep_all(const float* __restrict__ w_in, const float* __restrict__ wt1,
                            const float* __restrict__ rt1, const float* __restrict__ wt2,
                            const float* __restrict__ rt2) {
    int id = blockIdx.x * blockDim.x + threadIdx.x;
    if (id >= 256 * 256) return;
    int y = blockIdx.y;
    const float* W;
    int off;
    switch (y) {
        case 0: W = w_in;          off = OFF_WIN;           break;
        case 1: W = wt1;           off = OFF_R1;            break;
        case 2: W = wt1 + 65536;   off = OFF_R1 + 65536;    break;
        case 3: W = rt1;           off = OFF_R1 + 131072;   break;
        case 4: W = wt2;           off = OFF_R2;            break;
        case 5: W = wt2 + 65536;   off = OFF_R2 + 65536;    break;
        default: W = rt2;          off = OFF_R2 + 131072;   break;
    }
    wprep_one(W, 256, 256, off, id);
}

// ---------------- cp.async double-buffered fp16 GEMM (2-term B split) ---------
// AMODE 0: A = external fp32 (des/tweet merged, blockIdx.x selects), sync cvt stage.
// AMODE 1: A = fp16 slot (cp.async).
// cmode 0: writes fp16 x slot; cmode 1: rel segs -> g_hrel fp16, root -> g_hroot fp32.
template <int BN, int AMODE>
__global__ void __launch_bounds__(256) k_gemm_mma(
    const float* __restrict__ Ap0, const float* __restrict__ Ap1, int aSlot,
    int K, int M, int bOff,
    const float* __restrict__ bias0, const float* __restrict__ bias1,
    int cSel, int cbase, int cmode, int act)
{
    extern __shared__ char sm[];
    constexpr int STR = 144;
    constexpr int ABUF = 128 * STR;          // 18432: 128 rows x 64 fp16 (+pad)
    constexpr int BBUF = BN * STR;
    constexpr int NT = BN / 16;

    const uint32_t smb = smem_u32(sm);
    const int tid = threadIdx.x;
    const int lane = tid & 31, wid = tid >> 5;
    const int m_base = (wid & 3) * 32;
    const int n_base = (wid >> 2) * (BN / 2);

    const float* Aparam = (AMODE == 0 && blockIdx.x) ? Ap1 : Ap0;
    const float* bias = (AMODE == 0 && blockIdx.x) ? bias1 : bias0;
    const int cb = (AMODE == 0) ? (blockIdx.x ? cbase : 0) : cbase;
    const int boff_g = (AMODE == 0) ? (blockIdx.x ? OFF_TW : OFF_DES) : bOff;

    const __half* Ah = g_x + (size_t)aSlot * NP * HD;
    const __half* Bhi = g_whi + boff_g;
    const __half* Blo = g_wlo + boff_g;

    const int m0 = blockIdx.y * 128;
    const int n0 = (AMODE == 0) ? 0 : blockIdx.x * BN;
    const int nch = K >> 6;

    const int lrow = tid >> 1, lhalf = tid & 1;

    float acc[2][NT][4];
#pragma unroll
    for (int i = 0; i < 2; i++)
#pragma unroll
        for (int j = 0; j < NT; j++)
#pragma unroll
            for (int q = 0; q < 4; q++) acc[i][j][q] = 0.f;

    const uint32_t aoff = (uint32_t)(m_base + (lane & 15)) * STR + (uint32_t)(lane >> 4) * 16;
    const uint32_t boff = (uint32_t)(n_base + ((lane >> 4) & 1) * 8 + (lane & 7)) * STR +
                          (uint32_t)((lane >> 3) & 1) * 16;

    auto loadA = [&](int c, int buf) {
        if (AMODE == 1) {
            int k0 = c * 64;
            size_t base = (size_t)(m0 + lrow) * HD + k0 + lhalf * 32;
            uint32_t d = smb + buf * ABUF + lrow * STR + lhalf * 64;
#pragma unroll
            for (int j = 0; j < 4; j++)
                cpa16(d + j * 16, Ah + base + j * 8);
        }
    };
    auto loadB = [&](int c, int buf) {
        if (lrow < BN) {
            int k0 = c * 64;
            size_t base = (size_t)(n0 + lrow) * K + k0 + lhalf * 32;
            uint32_t d = smb + 2 * ABUF + buf * BBUF + lrow * STR + lhalf * 64;
            uint32_t d2 = d + 2 * BBUF;
#pragma unroll
            for (int j = 0; j < 4; j++) {
                cpa16(d + j * 16, Bhi + base + j * 8);
                cpa16(d2 + j * 16, Blo + base + j * 8);
            }
        }
    };

    loadA(0, 0);
    loadB(0, 0);
    cp_commit();

    for (int c = 0; c < nch; c++) {
        const int buf = c & 1;
        if (c + 1 < nch) {
            loadA(c + 1, buf ^ 1);
            loadB(c + 1, buf ^ 1);
            cp_commit();
            cp_wait<1>();
        } else {
            cp_wait<0>();
        }
        __syncthreads();

        if (AMODE == 0) {
            // synchronous fp32 -> fp16 stage into buffer `buf`
            int gr = m0 + lrow;
            int k0 = c * 64;
            uint4 h[4];
            if (gr < M) {
                const float4* srcp = (const float4*)(Aparam + (size_t)gr * K + k0 + lhalf * 32);
#pragma unroll
                for (int j = 0; j < 4; j++) h[j] = cvt8h(srcp[2 * j], srcp[2 * j + 1]);
            } else {
#pragma unroll
                for (int j = 0; j < 4; j++) h[j] = make_uint4(0, 0, 0, 0);
            }
#pragma unroll
            for (int j = 0; j < 4; j++)
                *(uint4*)(sm + buf * ABUF + lrow * STR + lhalf * 64 + j * 16) = h[j];
            __syncthreads();
        }

        const uint32_t ab  = smb + buf * ABUF;
        const uint32_t bbH = smb + 2 * ABUF + buf * BBUF;
        const uint32_t bbL = bbH + 2 * BBUF;

#pragma unroll
        for (int k16 = 0; k16 < 4; k16++) {
            uint32_t aH[2][4];
#pragma unroll
            for (int mi = 0; mi < 2; mi++)
                ldsm4(aH[mi], ab + aoff + mi * (16 * STR) + k16 * 32);
#pragma unroll
            for (int pr = 0; pr < NT / 2; pr++) {
                uint32_t bH[4], bL[4];
                uint32_t bd = boff + pr * (16 * STR) + k16 * 32;
                ldsm4(bH, bbH + bd);
                ldsm4(bL, bbL + bd);
#pragma unroll
                for (int mi = 0; mi < 2; mi++)
#pragma unroll
                    for (int t = 0; t < 2; t++) {
                        int nt = pr * 2 + t;
                        mma_f16(acc[mi][nt], aH[mi], bH + 2 * t);
                        mma_f16(acc[mi][nt], aH[mi], bL + 2 * t);
                    }
            }
        }
        __syncthreads();
    }

    // ---- epilogue ----
#pragma unroll
    for (int mi = 0; mi < 2; mi++) {
#pragma unroll
        for (int nt = 0; nt < NT; nt++) {
            int colL = n_base + nt * 8 + (lane & 3) * 2;
            int gcolL = n0 + colL;
            int bidx = (cmode == 1) ? (gcolL & 255) : colL;
            float b0 = bias[bidx], b1 = bias[bidx + 1];
#pragma unroll
            for (int half = 0; half < 2; half++) {
                int gr = m0 + m_base + mi * 16 + (lane >> 2) + half * 8;
                if (gr < M) {
                    float vx = actf(acc[mi][nt][half * 2 + 0] + b0, act);
                    float vy = actf(acc[mi][nt][half * 2 + 1] + b1, act);
                    __half2 hv = __floats2half2_rn(vx, vy);
                    if (cmode == 1) {
                        int seg = gcolL >> 8, lc = gcolL & 255;
                        if (seg < 2) {
                            *(__half2*)(g_hrel + ((size_t)seg * NN + gr) * 256 + lc) = hv;
                        } else {
                            *(float2*)(g_hroot + (size_t)gr * 256 + lc) = make_float2(vx, vy);
                        }
                    } else {
                        int slot = cSel - 1;
                        size_t eoff = (size_t)slot * NP * HD + (size_t)gr * HD + cb + gcolL;
                        *(__half2*)(g_x + eoff) = hv;
                    }
                }
            }
        }
    }
}

// ---------------- small projections (K=5 and K=3 merged) -> slot0 fp16 -------
__global__ void k_projsmall(const float* __restrict__ An, const float* __restrict__ Wn,
                            const float* __restrict__ bn,
                            const float* __restrict__ Ac, const float* __restrict__ Wc,
                            const float* __restrict__ bc)
{
    int id = blockIdx.x * blockDim.x + threadIdx.x;
    if (id >= NN * 64) return;
    int n = id >> 6, j = id & 63;
    const float* A = blockIdx.y ? Ac : An;
    const float* W = blockIdx.y ? Wc : Wn;
    const float* bias = blockIdx.y ? bc : bn;
    int K = blockIdx.y ? 3 : 5;
    int coloff = blockIdx.y ? 192 : 128;
    float s = bias[j];
    for (int k = 0; k < K; k++) s += A[(size_t)n * K + k] * W[k * 64 + j];
    s = actf(s, 1);
    g_x[(size_t)n * HD + coloff + j] = __float2half_rn(s);
}

// ---------------- CSR build ---------------------------------------------------
__global__ void k_zero_cnt() {
    int id = blockIdx.x * blockDim.x + threadIdx.x;
    if (id < 2 * NN) g_cnt[id] = 0;
}
__global__ void k_count(const int* __restrict__ dst, const int* __restrict__ et) {
    int e = blockIdx.x * blockDim.x + threadIdx.x;
    if (e >= EE) return;
    atomicAdd(&g_cnt[et[e] * NN + dst[e]], 1);
}
__global__ void k_scan() {
    __shared__ int part[1024];
    const int T = 1024;
    const int CH = (2 * NN + T - 1) / T;
    int t = threadIdx.x;
    int base = t * CH;
    int s = 0;
    for (int i = 0; i < CH; i++) {
        int idx = base + i;
        if (idx < 2 * NN) s += g_cnt[idx];
    }
    part[t] = s;
    __syncthreads();
    for (int off = 1; off < T; off <<= 1) {
        int v = (t >= off) ? part[t - off] : 0;
        __syncthreads();
        part[t] += v;
        __syncthreads();
    }
    int run = (t == 0) ? 0 : part[t - 1];
    for (int i = 0; i < CH; i++) {
        int idx = base + i;
        if (idx < 2 * NN) {
            g_off[idx] = run;
            g_cursor[idx] = run;
            run += g_cnt[idx];
        }
    }
    if (t == T - 1) g_off[2 * NN] = run;
}
__global__ void k_fill(const int* __restrict__ src, const int* __restrict__ dst,
                       const int* __restrict__ et) {
    int e = blockIdx.x * blockDim.x + threadIdx.x;
    if (e >= EE) return;
    int seg = et[e] * NN + dst[e];
    int pos = atomicAdd(&g_cursor[seg], 1);
    g_eidx[pos] = src[e];
}

// ---------------- fused gather-aggregate (one warp per node, fp16 messages) ---
// lane covers dims [lane*8, lane*8+8). FINAL=1: fused head logits.
template <int FINAL>
__global__ void __launch_bounds__(256) k_aggregate(int outSlot,
                                                   const float* __restrict__ Wout,
                                                   const float* __restrict__ bout,
                                                   float* __restrict__ out)
{
    int gw = (blockIdx.x * blockDim.x + threadIdx.x) >> 5;
    int lane = threadIdx.x & 31;
    if (gw >= NN) return;

    float a[8];
    {
        const float4* rootp = (const float4*)(g_hroot + (size_t)gw * HD + lane * 8);
        float4 r0 = rootp[0], r1 = rootp[1];
        a[0] = r0.x; a[1] = r0.y; a[2] = r0.z; a[3] = r0.w;
        a[4] = r1.x; a[5] = r1.y; a[6] = r1.z; a[7] = r1.w;
    }

#pragma unroll
    for (int rel = 0; rel < 2; rel++) {
        int s0 = g_off[rel * NN + gw];
        int s1 = g_off[rel * NN + gw + 1];
        float t[8];
#pragma unroll
        for (int q = 0; q < 8; q++) t[q] = 0.f;
        const __half* hb = g_hrel + (size_t)rel * NN * HD;
        int i = s0;
        for (; i + 1 < s1; i += 2) {
            int sn0 = g_eidx[i], sn1 = g_eidx[i + 1];
            uint4 w0 = *(const uint4*)(hb + (size_t)sn0 * HD + lane * 8);
            uint4 w1 = *(const uint4*)(hb + (size_t)sn1 * HD + lane * 8);
            const uint32_t* p0 = &w0.x;
            const uint32_t* p1 = &w1.x;
#pragma unroll
            for (int q = 0; q < 4; q++) {
                float2 f0 = __half22float2(*(const __half2*)&p0[q]);
                float2 f1 = __half22float2(*(const __half2*)&p1[q]);
                t[q * 2 + 0] += f0.x + f1.x;
                t[q * 2 + 1] += f0.y + f1.y;
            }
        }
        if (i < s1) {
            int sn = g_eidx[i];
            uint4 w0 = *(const uint4*)(hb + (size_t)sn * HD + lane * 8);
            const uint32_t* p0 = &w0.x;
#pragma unroll
            for (int q = 0; q < 4; q++) {
                float2 f0 = __half22float2(*(const __half2*)&p0[q]);
                t[q * 2 + 0] += f0.x;
                t[q * 2 + 1] += f0.y;
            }
        }
        int deg = s1 - s0;
        float inv = 1.f / (float)(deg > 0 ? deg : 1);
#pragma unroll
        for (int q = 0; q < 8; q++) a[q] += t[q] * inv;
    }

    if (FINAL == 0) {
        size_t eoff = (size_t)outSlot * NP * HD + (size_t)gw * HD + lane * 8;
        uint4 hv;
        *(__half2*)&hv.x = __floats2half2_rn(a[0], a[1]);
        *(__half2*)&hv.y = __floats2half2_rn(a[2], a[3]);
        *(__half2*)&hv.z = __floats2half2_rn(a[4], a[5]);
        *(__half2*)&hv.w = __floats2half2_rn(a[6], a[7]);
        *(uint4*)(g_x + eoff) = hv;
    } else {
        float s0 = 0.f, s1 = 0.f;
        int c0 = lane * 8;
#pragma unroll
        for (int q = 0; q < 8; q++) {
            float2 w = *(const float2*)(Wout + (c0 + q) * 2);
            s0 += a[q] * w.x;
            s1 += a[q] * w.y;
        }
#pragma unroll
        for (int o = 16; o; o >>= 1) {
            s0 += __shfl_down_sync(0xFFFFFFFFu, s0, o);
            s1 += __shfl_down_sync(0xFFFFFFFFu, s1, o);
        }
        if (lane == 0) {
            out[(size_t)gw * 2 + 0] = s0 + bout[0];
            out[(size_t)gw * 2 + 1] = s1 + bout[1];
        }
    }
}

// ---------------- launch ------------------------------------------------------
extern "C" void kernel_launch(void* const* d_in, const int* in_sizes, int n_in,
                              void* d_out, int out_size)
{
    const float* des   = (const float*)d_in[0];
    const float* tweet = (const float*)d_in[1];
    const float* nump  = (const float*)d_in[2];
    const float* catp  = (const float*)d_in[3];
    const int*   ei    = (const int*)d_in[4];
    const int*   et    = (const int*)d_in[5];
    const float* w_des = (const float*)d_in[6];
    const float* b_des = (const float*)d_in[7];
    const float* w_tw  = (const float*)d_in[8];
    const float* b_tw  = (const float*)d_in[9];
    const float* w_num = (const float*)d_in[10];
    const float* b_num = (const float*)d_in[11];
    const float* w_cat = (const float*)d_in[12];
    const float* b_cat = (const float*)d_in[13];
    const float* w_in  = (const float*)d_in[14];
    const float* b_in  = (const float*)d_in[15];
    const float* wt1   = (const float*)d_in[16];
    const float* rt1   = (const float*)d_in[17];
    const float* bs1   = (const float*)d_in[18];
    const float* wt2   = (const float*)d_in[19];
    const float* rt2   = (const float*)d_in[20];
    const float* bs2   = (const float*)d_in[21];
    const float* w_out = (const float*)d_in[22];
    const float* b_out = (const float*)d_in[23];
    float* out = (float*)d_out;

    const int* src = ei;
    const int* dst = ei + EE;

    const int SZ128 = 2 * 18432 + 4 * 128 * 144;    // 110592
    const int SZ64  = 2 * 18432 + 4 * 64 * 144;     // 73728
    cudaFuncSetAttribute(k_gemm_mma<128, 1>, cudaFuncAttributeMaxDynamicSharedMemorySize, SZ128);
    cudaFuncSetAttribute(k_gemm_mma<64, 0>,  cudaFuncAttributeMaxDynamicSharedMemorySize, SZ64);

    // weight prep (fp16 hi/lo transpose)
    k_wprep768<<<dim3((768 * 64 + 255) / 256, 2), 256>>>(w_des, w_tw);
    k_wprep_all<<<dim3((256 * 256 + 255) / 256, 7), 256>>>(w_in, wt1, rt1, wt2, rt2);

    // CSR build
    k_zero_cnt<<<(2 * NN + 255) / 256, 256>>>();
    k_count<<<(EE + 255) / 256, 256>>>(dst, et);
    k_scan<<<1, 1024>>>();
    k_fill<<<(EE + 255) / 256, 256>>>(src, dst, et);

    const int MB = (NN + 127) / 128;  // 391 row tiles

    // feature projections -> slot0 (des + tweet merged; num + cat merged)
    k_gemm_mma<64, 0><<<dim3(2, MB), 256, SZ64>>>(des, tweet, 0, 768, NN, 0,
                                                  b_des, b_tw, 1, 64, 0, 1);
    k_projsmall<<<dim3((NN * 64 + 255) / 256, 2), 256>>>(nump, w_num, b_num,
                                                         catp, w_cat, b_cat);

    // x = lrelu(slot0 @ w_in + b_in) -> slot1
    k_gemm_mma<128, 1><<<dim3(2, MB), 256, SZ128>>>(nullptr, nullptr, 0, 256, NN, OFF_WIN,
                                                    b_in, nullptr, 2, 0, 0, 1);

    const int agBl = (NN * 32 + 255) / 256;

    // RGCN layer 1: slot1 -> g_hrel/g_hroot -> slot0
    k_gemm_mma<128, 1><<<dim3(6, MB), 256, SZ128>>>(nullptr, nullptr, 1, 256, NN, OFF_R1,
                                                    bs1, nullptr, 3, 0, 1, 2);
    k_aggregate<0><<<agBl, 256>>>(0, nullptr, nullptr, nullptr);

    // RGCN layer 2: slot0 -> g_hrel/g_hroot -> head logits (fused)
    k_gemm_mma<128, 1><<<dim3(6, MB), 256, SZ128>>>(nullptr, nullptr, 0, 256, NN, OFF_R2,
                                                    bs2, nullptr, 3, 0, 1, 2);
    k_aggregate<1><<<agBl, 256>>>(0, w_out, b_out, out);
}

// round 13
// speedup vs baseline: 1.8754x; 1.2940x over previous
#include <cuda_runtime.h>
#include <cuda_bf16.h>
#include <cuda_fp16.h>
#include <cstdint>

#define NN 50000
#define NP 50048          // padded rows (multiple of 128) for unguarded cp.async
#define EE 800000
#define HD 256
#define DESW 768

// ---------------- scratch (device globals; no runtime alloc) ----------------
__device__ __align__(16) __half g_x[(size_t)2 * NP * HD];      // fp16 activations, 2 slots
__device__ __align__(16) __half g_hrel[(size_t)2 * NN * HD];   // fp16 messages
__device__ __align__(16) float  g_hroot[(size_t)NN * HD];      // fp32 root
__device__ __align__(16) int   g_cnt[2 * NN];
__device__ __align__(16) int   g_off[2 * NN + 1];
__device__ __align__(16) int   g_cursor[2 * NN];
__device__ __align__(16) int   g_eidx[EE];

#define OFF_DES 0
#define OFF_TW  49152
#define OFF_WIN 98304
#define OFF_R1  163840
#define OFF_R2  360448
__device__ __align__(16) __half g_w[557056];     // fp16 weights, transposed [N,K]

// ---------------- helpers -----------------------------------------------------
__device__ __forceinline__ uint32_t smem_u32(const void* p) {
    uint32_t a;
    asm("{ .reg .u64 t; cvta.to.shared.u64 t, %1; cvt.u32.u64 %0, t; }" : "=r"(a) : "l"(p));
    return a;
}
__device__ __forceinline__ void ldsm4(uint32_t* r, uint32_t addr) {
    asm volatile("ldmatrix.sync.aligned.m8n8.x4.shared.b16 {%0,%1,%2,%3}, [%4];"
                 : "=r"(r[0]), "=r"(r[1]), "=r"(r[2]), "=r"(r[3]) : "r"(addr));
}
__device__ __forceinline__ void mma_f16(float* c, const uint32_t* a, const uint32_t* b) {
    asm volatile(
        "mma.sync.aligned.m16n8k16.row.col.f32.f16.f16.f32 "
        "{%0,%1,%2,%3}, {%4,%5,%6,%7}, {%8,%9}, {%0,%1,%2,%3};"
        : "+f"(c[0]), "+f"(c[1]), "+f"(c[2]), "+f"(c[3])
        : "r"(a[0]), "r"(a[1]), "r"(a[2]), "r"(a[3]), "r"(b[0]), "r"(b[1]));
}
__device__ __forceinline__ void cpa16(uint32_t dst, const void* src) {
    asm volatile("cp.async.cg.shared.global [%0], [%1], 16;" :: "r"(dst), "l"(src));
}
__device__ __forceinline__ void cp_commit() {
    asm volatile("cp.async.commit_group;" ::: "memory");
}
template <int N>
__device__ __forceinline__ void cp_wait() {
    asm volatile("cp.async.wait_group %0;" :: "n"(N) : "memory");
}
__device__ __forceinline__ float actf(float v, int act) {
    if (act == 1) return v > 0.f ? v : 0.01f * v;
    if (act == 2) return v > 0.f ? v : 0.f;
    return v;
}
// 8 fp32 -> 8 fp16 packed in uint4
__device__ __forceinline__ uint4 cvt8h(float4 x, float4 y) {
    uint4 r;
    *(__half2*)&r.x = __floats2half2_rn(x.x, x.y);
    *(__half2*)&r.y = __floats2half2_rn(x.z, x.w);
    *(__half2*)&r.z = __floats2half2_rn(y.x, y.y);
    *(__half2*)&r.w = __floats2half2_rn(y.z, y.w);
    return r;
}

// ---------------- weight prep: W[K,N] fp32 -> fp16 transposed ----------------
__device__ __forceinline__ void wprep_one(const float* W, int K, int N, int outOff, int id) {
    int k = id / N, n = id - k * N;
    g_w[(size_t)outOff + (size_t)n * K + k] = __float2half_rn(W[id]);
}
__global__ void k_wprep768(const float* __restrict__ Wd, const float* __restrict__ Wt) {
    int id = blockIdx.x * blockDim.x + threadIdx.x;
    if (id >= 768 * 64) return;
    wprep_one(blockIdx.y ? Wt : Wd, 768, 64, blockIdx.y ? OFF_TW : OFF_DES, id);
}
__global__ void k_wprep_all(const float* __restrict__ w_in, const float* __restrict__ wt1,
                            const float* __restrict__ rt1, const float* __restrict__ wt2,
                            const float* __restrict__ rt2) {
    int id = blockIdx.x * blockDim.x + threadIdx.x;
    if (id >= 256 * 256) return;
    int y = blockIdx.y;
    const float* W;
    int off;
    switch (y) {
        case 0: W = w_in;          off = OFF_WIN;           break;
        case 1: W = wt1;           off = OFF_R1;            break;
        case 2: W = wt1 + 65536;   off = OFF_R1 + 65536;    break;
        case 3: W = rt1;           off = OFF_R1 + 131072;   break;
        case 4: W = wt2;           off = OFF_R2;            break;
        case 5: W = wt2 + 65536;   off = OFF_R2 + 65536;    break;
        default: W = rt2;          off = OFF_R2 + 131072;   break;
    }
    wprep_one(W, 256, 256, off, id);
}

// ---------------- cp.async double-buffered pure-fp16 GEMM ---------------------
// AMODE 0: A = external fp32 (des/tweet merged, blockIdx.x selects), sync cvt stage.
// AMODE 1: A = fp16 slot (cp.async).
// cmode 0: writes fp16 x slot; cmode 1: rel segs -> g_hrel fp16, root -> g_hroot fp32.
template <int BN, int AMODE>
__global__ void __launch_bounds__(256) k_gemm_mma(
    const float* __restrict__ Ap0, const float* __restrict__ Ap1, int aSlot,
    int K, int M, int bOff,
    const float* __restrict__ bias0, const float* __restrict__ bias1,
    int cSel, int cbase, int cmode, int act)
{
    extern __shared__ char sm[];
    constexpr int STR = 144;
    constexpr int ABUF = 128 * STR;          // 18432: 128 rows x 64 fp16 (+pad)
    constexpr int BBUF = BN * STR;
    constexpr int NT = BN / 16;

    const uint32_t smb = smem_u32(sm);
    const int tid = threadIdx.x;
    const int lane = tid & 31, wid = tid >> 5;
    const int m_base = (wid & 3) * 32;
    const int n_base = (wid >> 2) * (BN / 2);

    const float* Aparam = (AMODE == 0 && blockIdx.x) ? Ap1 : Ap0;
    const float* bias = (AMODE == 0 && blockIdx.x) ? bias1 : bias0;
    const int cb = (AMODE == 0) ? (blockIdx.x ? cbase : 0) : cbase;
    const int boff_g = (AMODE == 0) ? (blockIdx.x ? OFF_TW : OFF_DES) : bOff;

    const __half* Ah = g_x + (size_t)aSlot * NP * HD;
    const __half* B = g_w + boff_g;

    const int m0 = blockIdx.y * 128;
    const int n0 = (AMODE == 0) ? 0 : blockIdx.x * BN;
    const int nch = K >> 6;

    const int lrow = tid >> 1, lhalf = tid & 1;

    float acc[2][NT][4];
#pragma unroll
    for (int i = 0; i < 2; i++)
#pragma unroll
        for (int j = 0; j < NT; j++)
#pragma unroll
            for (int q = 0; q < 4; q++) acc[i][j][q] = 0.f;

    const uint32_t aoff = (uint32_t)(m_base + (lane & 15)) * STR + (uint32_t)(lane >> 4) * 16;
    const uint32_t boff = (uint32_t)(n_base + ((lane >> 4) & 1) * 8 + (lane & 7)) * STR +
                          (uint32_t)((lane >> 3) & 1) * 16;

    auto loadA = [&](int c, int buf) {
        if (AMODE == 1) {
            int k0 = c * 64;
            size_t base = (size_t)(m0 + lrow) * HD + k0 + lhalf * 32;
            uint32_t d = smb + buf * ABUF + lrow * STR + lhalf * 64;
#pragma unroll
            for (int j = 0; j < 4; j++)
                cpa16(d + j * 16, Ah + base + j * 8);
        }
    };
    auto loadB = [&](int c, int buf) {
        if (lrow < BN) {
            int k0 = c * 64;
            size_t base = (size_t)(n0 + lrow) * K + k0 + lhalf * 32;
            uint32_t d = smb + 2 * ABUF + buf * BBUF + lrow * STR + lhalf * 64;
#pragma unroll
            for (int j = 0; j < 4; j++)
                cpa16(d + j * 16, B + base + j * 8);
        }
    };

    loadA(0, 0);
    loadB(0, 0);
    cp_commit();

    for (int c = 0; c < nch; c++) {
        const int buf = c & 1;
        if (c + 1 < nch) {
            loadA(c + 1, buf ^ 1);
            loadB(c + 1, buf ^ 1);
            cp_commit();
            cp_wait<1>();
        } else {
            cp_wait<0>();
        }
        __syncthreads();

        if (AMODE == 0) {
            // synchronous fp32 -> fp16 stage into buffer `buf`
            int gr = m0 + lrow;
            int k0 = c * 64;
            uint4 h[4];
            if (gr < M) {
                const float4* srcp = (const float4*)(Aparam + (size_t)gr * K + k0 + lhalf * 32);
#pragma unroll
                for (int j = 0; j < 4; j++) h[j] = cvt8h(srcp[2 * j], srcp[2 * j + 1]);
            } else {
#pragma unroll
                for (int j = 0; j < 4; j++) h[j] = make_uint4(0, 0, 0, 0);
            }
#pragma unroll
            for (int j = 0; j < 4; j++)
                *(uint4*)(sm + buf * ABUF + lrow * STR + lhalf * 64 + j * 16) = h[j];
            __syncthreads();
        }

        const uint32_t ab = smb + buf * ABUF;
        const uint32_t bb = smb + 2 * ABUF + buf * BBUF;

#pragma unroll
        for (int k16 = 0; k16 < 4; k16++) {
            uint32_t aH[2][4];
#pragma unroll
            for (int mi = 0; mi < 2; mi++)
                ldsm4(aH[mi], ab + aoff + mi * (16 * STR) + k16 * 32);
#pragma unroll
            for (int pr = 0; pr < NT / 2; pr++) {
                uint32_t bH[4];
                ldsm4(bH, bb + boff + pr * (16 * STR) + k16 * 32);
#pragma unroll
                for (int mi = 0; mi < 2; mi++)
#pragma unroll
                    for (int t = 0; t < 2; t++)
                        mma_f16(acc[mi][pr * 2 + t], aH[mi], bH + 2 * t);
            }
        }
        __syncthreads();
    }

    // ---- epilogue ----
#pragma unroll
    for (int mi = 0; mi < 2; mi++) {
#pragma unroll
        for (int nt = 0; nt < NT; nt++) {
            int colL = n_base + nt * 8 + (lane & 3) * 2;
            int gcolL = n0 + colL;
            int bidx = (cmode == 1) ? (gcolL & 255) : colL;
            float b0 = bias[bidx], b1 = bias[bidx + 1];
#pragma unroll
            for (int half = 0; half < 2; half++) {
                int gr = m0 + m_base + mi * 16 + (lane >> 2) + half * 8;
                if (gr < M) {
                    float vx = actf(acc[mi][nt][half * 2 + 0] + b0, act);
                    float vy = actf(acc[mi][nt][half * 2 + 1] + b1, act);
                    __half2 hv = __floats2half2_rn(vx, vy);
                    if (cmode == 1) {
                        int seg = gcolL >> 8, lc = gcolL & 255;
                        if (seg < 2) {
                            *(__half2*)(g_hrel + ((size_t)seg * NN + gr) * 256 + lc) = hv;
                        } else {
                            *(float2*)(g_hroot + (size_t)gr * 256 + lc) = make_float2(vx, vy);
                        }
                    } else {
                        int slot = cSel - 1;
                        size_t eoff = (size_t)slot * NP * HD + (size_t)gr * HD + cb + gcolL;
                        *(__half2*)(g_x + eoff) = hv;
                    }
                }
            }
        }
    }
}

// ---------------- small projections (K=5 and K=3 merged) -> slot0 fp16 -------
__global__ void k_projsmall(const float* __restrict__ An, const float* __restrict__ Wn,
                            const float* __restrict__ bn,
                            const float* __restrict__ Ac, const float* __restrict__ Wc,
                            const float* __restrict__ bc)
{
    int id = blockIdx.x * blockDim.x + threadIdx.x;
    if (id >= NN * 64) return;
    int n = id >> 6, j = id & 63;
    const float* A = blockIdx.y ? Ac : An;
    const float* W = blockIdx.y ? Wc : Wn;
    const float* bias = blockIdx.y ? bc : bn;
    int K = blockIdx.y ? 3 : 5;
    int coloff = blockIdx.y ? 192 : 128;
    float s = bias[j];
    for (int k = 0; k < K; k++) s += A[(size_t)n * K + k] * W[k * 64 + j];
    s = actf(s, 1);
    g_x[(size_t)n * HD + coloff + j] = __float2half_rn(s);
}

// ---------------- CSR build ---------------------------------------------------
__global__ void k_zero_cnt() {
    int id = blockIdx.x * blockDim.x + threadIdx.x;
    if (id < 2 * NN) g_cnt[id] = 0;
}
__global__ void k_count(const int* __restrict__ dst, const int* __restrict__ et) {
    int e = blockIdx.x * blockDim.x + threadIdx.x;
    if (e >= EE) return;
    atomicAdd(&g_cnt[et[e] * NN + dst[e]], 1);
}
__global__ void k_scan() {
    __shared__ int part[1024];
    const int T = 1024;
    const int CH = (2 * NN + T - 1) / T;
    int t = threadIdx.x;
    int base = t * CH;
    int s = 0;
    for (int i = 0; i < CH; i++) {
        int idx = base + i;
        if (idx < 2 * NN) s += g_cnt[idx];
    }
    part[t] = s;
    __syncthreads();
    for (int off = 1; off < T; off <<= 1) {
        int v = (t >= off) ? part[t - off] : 0;
        __syncthreads();
        part[t] += v;
        __syncthreads();
    }
    int run = (t == 0) ? 0 : part[t - 1];
    for (int i = 0; i < CH; i++) {
        int idx = base + i;
        if (idx < 2 * NN) {
            g_off[idx] = run;
            g_cursor[idx] = run;
            run += g_cnt[idx];
        }
    }
    if (t == T - 1) g_off[2 * NN] = run;
}
__global__ void k_fill(const int* __restrict__ src, const int* __restrict__ dst,
                       const int* __restrict__ et) {
    int e = blockIdx.x * blockDim.x + threadIdx.x;
    if (e >= EE) return;
    int seg = et[e] * NN + dst[e];
    int pos = atomicAdd(&g_cursor[seg], 1);
    g_eidx[pos] = src[e];
}

// ---------------- fused gather-aggregate (one warp per node, fp16 messages) ---
// lane covers dims [lane*8, lane*8+8). FINAL=1: fused head logits.
template <int FINAL>
__global__ void __launch_bounds__(256) k_aggregate(int outSlot,
                                                   const float* __restrict__ Wout,
                                                   const float* __restrict__ bout,
                                                   float* __restrict__ out)
{
    int gw = (blockIdx.x * blockDim.x + threadIdx.x) >> 5;
    int lane = threadIdx.x & 31;
    if (gw >= NN) return;

    float a[8];
    {
        const float4* rootp = (const float4*)(g_hroot + (size_t)gw * HD + lane * 8);
        float4 r0 = rootp[0], r1 = rootp[1];
        a[0] = r0.x; a[1] = r0.y; a[2] = r0.z; a[3] = r0.w;
        a[4] = r1.x; a[5] = r1.y; a[6] = r1.z; a[7] = r1.w;
    }

#pragma unroll
    for (int rel = 0; rel < 2; rel++) {
        int s0 = g_off[rel * NN + gw];
        int s1 = g_off[rel * NN + gw + 1];
        float t[8];
#pragma unroll
        for (int q = 0; q < 8; q++) t[q] = 0.f;
        const __half* hb = g_hrel + (size_t)rel * NN * HD;
        int i = s0;
        for (; i + 1 < s1; i += 2) {
            int sn0 = g_eidx[i], sn1 = g_eidx[i + 1];
            uint4 w0 = *(const uint4*)(hb + (size_t)sn0 * HD + lane * 8);
            uint4 w1 = *(const uint4*)(hb + (size_t)sn1 * HD + lane * 8);
            const uint32_t* p0 = &w0.x;
            const uint32_t* p1 = &w1.x;
#pragma unroll
            for (int q = 0; q < 4; q++) {
                float2 f0 = __half22float2(*(const __half2*)&p0[q]);
                float2 f1 = __half22float2(*(const __half2*)&p1[q]);
                t[q * 2 + 0] += f0.x + f1.x;
                t[q * 2 + 1] += f0.y + f1.y;
            }
        }
        if (i < s1) {
            int sn = g_eidx[i];
            uint4 w0 = *(const uint4*)(hb + (size_t)sn * HD + lane * 8);
            const uint32_t* p0 = &w0.x;
#pragma unroll
            for (int q = 0; q < 4; q++) {
                float2 f0 = __half22float2(*(const __half2*)&p0[q]);
                t[q * 2 + 0] += f0.x;
                t[q * 2 + 1] += f0.y;
            }
        }
        int deg = s1 - s0;
        float inv = 1.f / (float)(deg > 0 ? deg : 1);
#pragma unroll
        for (int q = 0; q < 8; q++) a[q] += t[q] * inv;
    }

    if (FINAL == 0) {
        size_t eoff = (size_t)outSlot * NP * HD + (size_t)gw * HD + lane * 8;
        uint4 hv;
        *(__half2*)&hv.x = __floats2half2_rn(a[0], a[1]);
        *(__half2*)&hv.y = __floats2half2_rn(a[2], a[3]);
        *(__half2*)&hv.z = __floats2half2_rn(a[4], a[5]);
        *(__half2*)&hv.w = __floats2half2_rn(a[6], a[7]);
        *(uint4*)(g_x + eoff) = hv;
    } else {
        float s0 = 0.f, s1 = 0.f;
        int c0 = lane * 8;
#pragma unroll
        for (int q = 0; q < 8; q++) {
            float2 w = *(const float2*)(Wout + (c0 + q) * 2);
            s0 += a[q] * w.x;
            s1 += a[q] * w.y;
        }
#pragma unroll
        for (int o = 16; o; o >>= 1) {
            s0 += __shfl_down_sync(0xFFFFFFFFu, s0, o);
            s1 += __shfl_down_sync(0xFFFFFFFFu, s1, o);
        }
        if (lane == 0) {
            out[(size_t)gw * 2 + 0] = s0 + bout[0];
            out[(size_t)gw * 2 + 1] = s1 + bout[1];
        }
    }
}

// ---------------- launch ------------------------------------------------------
extern "C" void kernel_launch(void* const* d_in, const int* in_sizes, int n_in,
                              void* d_out, int out_size)
{
    const float* des   = (const float*)d_in[0];
    const float* tweet = (const float*)d_in[1];
    const float* nump  = (const float*)d_in[2];
    const float* catp  = (const float*)d_in[3];
    const int*   ei    = (const int*)d_in[4];
    const int*   et    = (const int*)d_in[5];
    const float* w_des = (const float*)d_in[6];
    const float* b_des = (const float*)d_in[7];
    const float* w_tw  = (const float*)d_in[8];
    const float* b_tw  = (const float*)d_in[9];
    const float* w_num = (const float*)d_in[10];
    const float* b_num = (const float*)d_in[11];
    const float* w_cat = (const float*)d_in[12];
    const float* b_cat = (const float*)d_in[13];
    const float* w_in  = (const float*)d_in[14];
    const float* b_in  = (const float*)d_in[15];
    const float* wt1   = (const float*)d_in[16];
    const float* rt1   = (const float*)d_in[17];
    const float* bs1   = (const float*)d_in[18];
    const float* wt2   = (const float*)d_in[19];
    const float* rt2   = (const float*)d_in[20];
    const float* bs2   = (const float*)d_in[21];
    const float* w_out = (const float*)d_in[22];
    const float* b_out = (const float*)d_in[23];
    float* out = (float*)d_out;

    const int* src = ei;
    const int* dst = ei + EE;

    const int SZ128 = 2 * 18432 + 2 * 128 * 144;    // 73728
    const int SZ64  = 2 * 18432 + 2 * 64 * 144;     // 55296
    cudaFuncSetAttribute(k_gemm_mma<128, 1>, cudaFuncAttributeMaxDynamicSharedMemorySize, SZ128);
    cudaFuncSetAttribute(k_gemm_mma<64, 0>,  cudaFuncAttributeMaxDynamicSharedMemorySize, SZ64);

    // weight prep (fp16 transpose)
    k_wprep768<<<dim3((768 * 64 + 255) / 256, 2), 256>>>(w_des, w_tw);
    k_wprep_all<<<dim3((256 * 256 + 255) / 256, 7), 256>>>(w_in, wt1, rt1, wt2, rt2);

    // CSR build
    k_zero_cnt<<<(2 * NN + 255) / 256, 256>>>();
    k_count<<<(EE + 255) / 256, 256>>>(dst, et);
    k_scan<<<1, 1024>>>();
    k_fill<<<(EE + 255) / 256, 256>>>(src, dst, et);

    const int MB = (NN + 127) / 128;  // 391 row tiles

    // feature projections -> slot0 (des + tweet merged; num + cat merged)
    k_gemm_mma<64, 0><<<dim3(2, MB), 256, SZ64>>>(des, tweet, 0, 768, NN, 0,
                                                  b_des, b_tw, 1, 64, 0, 1);
    k_projsmall<<<dim3((NN * 64 + 255) / 256, 2), 256>>>(nump, w_num, b_num,
                                                         catp, w_cat, b_cat);

    // x = lrelu(slot0 @ w_in + b_in) -> slot1
    k_gemm_mma<128, 1><<<dim3(2, MB), 256, SZ128>>>(nullptr, nullptr, 0, 256, NN, OFF_WIN,
                                                    b_in, nullptr, 2, 0, 0, 1);

    const int agBl = (NN * 32 + 255) / 256;

    // RGCN layer 1: slot1 -> g_hrel/g_hroot -> slot0
    k_gemm_mma<128, 1><<<dim3(6, MB), 256, SZ128>>>(nullptr, nullptr, 1, 256, NN, OFF_R1,
                                                    bs1, nullptr, 3, 0, 1, 2);
    k_aggregate<0><<<agBl, 256>>>(0, nullptr, nullptr, nullptr);

    // RGCN layer 2: slot0 -> g_hrel/g_hroot -> head logits (fused)
    k_gemm_mma<128, 1><<<dim3(6, MB), 256, SZ128>>>(nullptr, nullptr, 0, 256, NN, OFF_R2,
                                                    bs2, nullptr, 3, 0, 1, 2);
    k_aggregate<1><<<agBl, 256>>>(0, w_out, b_out, out);
}

// round 14
// speedup vs baseline: 1.8916x; 1.0086x over previous
#include <cuda_runtime.h>
#include <cuda_bf16.h>
#include <cuda_fp16.h>
#include <cstdint>

#define NN 50000
#define NP 50048          // padded rows (multiple of 128) for unguarded cp.async
#define EE 800000
#define HD 256
#define DESW 768

// ---------------- scratch (device globals; no runtime alloc) ----------------
__device__ __align__(16) __half g_x[(size_t)2 * NP * HD];      // fp16 activations, 2 slots
__device__ __align__(16) __half g_hrel[(size_t)2 * NN * HD];   // fp16 messages
__device__ __align__(16) float  g_hroot[(size_t)NN * HD];      // fp32 root
__device__ __align__(16) int   g_cnt[2 * NN];
__device__ __align__(16) int   g_off[2 * NN + 1];
__device__ __align__(16) int   g_cursor[2 * NN];
__device__ __align__(16) int   g_eidx[EE];

#define OFF_DES 0
#define OFF_TW  49152
#define OFF_WIN 98304
#define OFF_R1  163840
#define OFF_R2  360448
__device__ __align__(16) __half g_w[557056];     // fp16 weights, transposed [N,K]

// ---------------- helpers -----------------------------------------------------
__device__ __forceinline__ uint32_t smem_u32(const void* p) {
    uint32_t a;
    asm("{ .reg .u64 t; cvta.to.shared.u64 t, %1; cvt.u32.u64 %0, t; }" : "=r"(a) : "l"(p));
    return a;
}
__device__ __forceinline__ void ldsm4(uint32_t* r, uint32_t addr) {
    asm volatile("ldmatrix.sync.aligned.m8n8.x4.shared.b16 {%0,%1,%2,%3}, [%4];"
                 : "=r"(r[0]), "=r"(r[1]), "=r"(r[2]), "=r"(r[3]) : "r"(addr));
}
__device__ __forceinline__ void mma_f16(float* c, const uint32_t* a, const uint32_t* b) {
    asm volatile(
        "mma.sync.aligned.m16n8k16.row.col.f32.f16.f16.f32 "
        "{%0,%1,%2,%3}, {%4,%5,%6,%7}, {%8,%9}, {%0,%1,%2,%3};"
        : "+f"(c[0]), "+f"(c[1]), "+f"(c[2]), "+f"(c[3])
        : "r"(a[0]), "r"(a[1]), "r"(a[2]), "r"(a[3]), "r"(b[0]), "r"(b[1]));
}
__device__ __forceinline__ void cpa16(uint32_t dst, const void* src) {
    asm volatile("cp.async.cg.shared.global [%0], [%1], 16;" :: "r"(dst), "l"(src));
}
__device__ __forceinline__ void cp_commit() {
    asm volatile("cp.async.commit_group;" ::: "memory");
}
template <int N>
__device__ __forceinline__ void cp_wait() {
    asm volatile("cp.async.wait_group %0;" :: "n"(N) : "memory");
}
__device__ __forceinline__ float actf(float v, int act) {
    if (act == 1) return v > 0.f ? v : 0.01f * v;
    if (act == 2) return v > 0.f ? v : 0.f;
    return v;
}
// 8 fp32 -> 8 fp16 packed in uint4
__device__ __forceinline__ uint4 cvt8h(float4 x, float4 y) {
    uint4 r;
    *(__half2*)&r.x = __floats2half2_rn(x.x, x.y);
    *(__half2*)&r.y = __floats2half2_rn(x.z, x.w);
    *(__half2*)&r.z = __floats2half2_rn(y.x, y.y);
    *(__half2*)&r.w = __floats2half2_rn(y.z, y.w);
    return r;
}

// ---------------- weight prep: all 9 matrices in ONE launch -------------------
// grid.y: 0=w_des 1=w_tw (768x64); 2=w_in 3,4=wt1 5=rt1 6,7=wt2 8=rt2 (256x256)
__global__ void k_wprep(const float* __restrict__ w_des, const float* __restrict__ w_tw,
                        const float* __restrict__ w_in, const float* __restrict__ wt1,
                        const float* __restrict__ rt1, const float* __restrict__ wt2,
                        const float* __restrict__ rt2) {
    int id = blockIdx.x * blockDim.x + threadIdx.x;
    int y = blockIdx.y;
    const float* W;
    int off, K, N;
    switch (y) {
        case 0: W = w_des;         off = OFF_DES;           K = 768; N = 64;  break;
        case 1: W = w_tw;          off = OFF_TW;            K = 768; N = 64;  break;
        case 2: W = w_in;          off = OFF_WIN;           K = 256; N = 256; break;
        case 3: W = wt1;           off = OFF_R1;            K = 256; N = 256; break;
        case 4: W = wt1 + 65536;   off = OFF_R1 + 65536;    K = 256; N = 256; break;
        case 5: W = rt1;           off = OFF_R1 + 131072;   K = 256; N = 256; break;
        case 6: W = wt2;           off = OFF_R2;            K = 256; N = 256; break;
        case 7: W = wt2 + 65536;   off = OFF_R2 + 65536;    K = 256; N = 256; break;
        default: W = rt2;          off = OFF_R2 + 131072;   K = 256; N = 256; break;
    }
    if (id >= K * N) return;
    int k = id / N, n = id - k * N;
    g_w[(size_t)off + (size_t)n * K + k] = __float2half_rn(W[id]);
}

// ---------------- cp.async double-buffered pure-fp16 GEMM ---------------------
// AMODE 0: A = external fp32 (des/tweet merged, blockIdx.x selects);
//          fp32 rows software-pipelined through registers (LDG c+1 under MMA c).
// AMODE 1: A = fp16 slot (cp.async).
// cmode 0: writes fp16 x slot; cmode 1: rel segs -> g_hrel fp16, root -> g_hroot fp32.
template <int BN, int AMODE>
__global__ void __launch_bounds__(256) k_gemm_mma(
    const float* __restrict__ Ap0, const float* __restrict__ Ap1, int aSlot,
    int K, int M, int bOff,
    const float* __restrict__ bias0, const float* __restrict__ bias1,
    int cSel, int cbase, int cmode, int act)
{
    extern __shared__ char sm[];
    constexpr int STR = 144;
    constexpr int ABUF = 128 * STR;          // 18432: 128 rows x 64 fp16 (+pad)
    constexpr int BBUF = BN * STR;
    constexpr int NT = BN / 16;

    const uint32_t smb = smem_u32(sm);
    const int tid = threadIdx.x;
    const int lane = tid & 31, wid = tid >> 5;
    const int m_base = (wid & 3) * 32;
    const int n_base = (wid >> 2) * (BN / 2);

    const float* Aparam = (AMODE == 0 && blockIdx.x) ? Ap1 : Ap0;
    const float* bias = (AMODE == 0 && blockIdx.x) ? bias1 : bias0;
    const int cb = (AMODE == 0) ? (blockIdx.x ? cbase : 0) : cbase;
    const int boff_g = (AMODE == 0) ? (blockIdx.x ? OFF_TW : OFF_DES) : bOff;

    const __half* Ah = g_x + (size_t)aSlot * NP * HD;
    const __half* B = g_w + boff_g;

    const int m0 = blockIdx.y * 128;
    const int n0 = (AMODE == 0) ? 0 : blockIdx.x * BN;
    const int nch = K >> 6;

    const int lrow = tid >> 1, lhalf = tid & 1;

    float acc[2][NT][4];
#pragma unroll
    for (int i = 0; i < 2; i++)
#pragma unroll
        for (int j = 0; j < NT; j++)
#pragma unroll
            for (int q = 0; q < 4; q++) acc[i][j][q] = 0.f;

    const uint32_t aoff = (uint32_t)(m_base + (lane & 15)) * STR + (uint32_t)(lane >> 4) * 16;
    const uint32_t boff = (uint32_t)(n_base + ((lane >> 4) & 1) * 8 + (lane & 7)) * STR +
                          (uint32_t)((lane >> 3) & 1) * 16;

    // register staging for AMODE 0 fp32 A rows (software pipeline)
    float4 areg[8];
    auto load_regs = [&](int c) {
        if (AMODE == 0) {
            int gr = m0 + lrow;
            if (gr < M) {
                const float4* srcp = (const float4*)(Aparam + (size_t)gr * K + c * 64 + lhalf * 32);
#pragma unroll
                for (int j = 0; j < 8; j++) areg[j] = srcp[j];
            } else {
#pragma unroll
                for (int j = 0; j < 8; j++) areg[j] = make_float4(0.f, 0.f, 0.f, 0.f);
            }
        }
    };

    auto loadA = [&](int c, int buf) {
        if (AMODE == 1) {
            int k0 = c * 64;
            size_t base = (size_t)(m0 + lrow) * HD + k0 + lhalf * 32;
            uint32_t d = smb + buf * ABUF + lrow * STR + lhalf * 64;
#pragma unroll
            for (int j = 0; j < 4; j++)
                cpa16(d + j * 16, Ah + base + j * 8);
        }
    };
    auto loadB = [&](int c, int buf) {
        if (lrow < BN) {
            int k0 = c * 64;
            size_t base = (size_t)(n0 + lrow) * K + k0 + lhalf * 32;
            uint32_t d = smb + 2 * ABUF + buf * BBUF + lrow * STR + lhalf * 64;
#pragma unroll
            for (int j = 0; j < 4; j++)
                cpa16(d + j * 16, B + base + j * 8);
        }
    };

    loadA(0, 0);
    loadB(0, 0);
    cp_commit();
    load_regs(0);

    for (int c = 0; c < nch; c++) {
        const int buf = c & 1;
        if (c + 1 < nch) {
            loadA(c + 1, buf ^ 1);
            loadB(c + 1, buf ^ 1);
            cp_commit();
            cp_wait<1>();
        } else {
            cp_wait<0>();
        }
        __syncthreads();

        if (AMODE == 0) {
            // cvt staged regs -> fp16 smem, then issue next chunk's LDGs (overlap w/ MMA)
            uint4 h[4];
#pragma unroll
            for (int j = 0; j < 4; j++) h[j] = cvt8h(areg[2 * j], areg[2 * j + 1]);
#pragma unroll
            for (int j = 0; j < 4; j++)
                *(uint4*)(sm + buf * ABUF + lrow * STR + lhalf * 64 + j * 16) = h[j];
            if (c + 1 < nch) load_regs(c + 1);
            __syncthreads();
        }

        const uint32_t ab = smb + buf * ABUF;
        const uint32_t bb = smb + 2 * ABUF + buf * BBUF;

#pragma unroll
        for (int k16 = 0; k16 < 4; k16++) {
            uint32_t aH[2][4];
#pragma unroll
            for (int mi = 0; mi < 2; mi++)
                ldsm4(aH[mi], ab + aoff + mi * (16 * STR) + k16 * 32);
#pragma unroll
            for (int pr = 0; pr < NT / 2; pr++) {
                uint32_t bH[4];
                ldsm4(bH, bb + boff + pr * (16 * STR) + k16 * 32);
#pragma unroll
                for (int mi = 0; mi < 2; mi++)
#pragma unroll
                    for (int t = 0; t < 2; t++)
                        mma_f16(acc[mi][pr * 2 + t], aH[mi], bH + 2 * t);
            }
        }
        __syncthreads();
    }

    // ---- epilogue ----
#pragma unroll
    for (int mi = 0; mi < 2; mi++) {
#pragma unroll
        for (int nt = 0; nt < NT; nt++) {
            int colL = n_base + nt * 8 + (lane & 3) * 2;
            int gcolL = n0 + colL;
            int bidx = (cmode == 1) ? (gcolL & 255) : colL;
            float b0 = bias[bidx], b1 = bias[bidx + 1];
#pragma unroll
            for (int half = 0; half < 2; half++) {
                int gr = m0 + m_base + mi * 16 + (lane >> 2) + half * 8;
                if (gr < M) {
                    float vx = actf(acc[mi][nt][half * 2 + 0] + b0, act);
                    float vy = actf(acc[mi][nt][half * 2 + 1] + b1, act);
                    __half2 hv = __floats2half2_rn(vx, vy);
                    if (cmode == 1) {
                        int seg = gcolL >> 8, lc = gcolL & 255;
                        if (seg < 2) {
                            *(__half2*)(g_hrel + ((size_t)seg * NN + gr) * 256 + lc) = hv;
                        } else {
                            *(float2*)(g_hroot + (size_t)gr * 256 + lc) = make_float2(vx, vy);
                        }
                    } else {
                        int slot = cSel - 1;
                        size_t eoff = (size_t)slot * NP * HD + (size_t)gr * HD + cb + gcolL;
                        *(__half2*)(g_x + eoff) = hv;
                    }
                }
            }
        }
    }
}

// ---------------- small projections (K=5 and K=3 merged) -> slot0 fp16 -------
__global__ void k_projsmall(const float* __restrict__ An, const float* __restrict__ Wn,
                            const float* __restrict__ bn,
                            const float* __restrict__ Ac, const float* __restrict__ Wc,
                            const float* __restrict__ bc)
{
    int id = blockIdx.x * blockDim.x + threadIdx.x;
    if (id >= NN * 64) return;
    int n = id >> 6, j = id & 63;
    const float* A = blockIdx.y ? Ac : An;
    const float* W = blockIdx.y ? Wc : Wn;
    const float* bias = blockIdx.y ? bc : bn;
    int K = blockIdx.y ? 3 : 5;
    int coloff = blockIdx.y ? 192 : 128;
    float s = bias[j];
    for (int k = 0; k < K; k++) s += A[(size_t)n * K + k] * W[k * 64 + j];
    s = actf(s, 1);
    g_x[(size_t)n * HD + coloff + j] = __float2half_rn(s);
}

// ---------------- CSR build ---------------------------------------------------
__global__ void k_zero_cnt() {
    int id = blockIdx.x * blockDim.x + threadIdx.x;
    if (id < 2 * NN) g_cnt[id] = 0;
}
__global__ void k_count(const int* __restrict__ dst, const int* __restrict__ et) {
    int e = blockIdx.x * blockDim.x + threadIdx.x;
    if (e >= EE) return;
    atomicAdd(&g_cnt[et[e] * NN + dst[e]], 1);
}
__global__ void k_scan() {
    __shared__ int part[1024];
    const int T = 1024;
    const int CH = (2 * NN + T - 1) / T;
    int t = threadIdx.x;
    int base = t * CH;
    int s = 0;
    for (int i = 0; i < CH; i++) {
        int idx = base + i;
        if (idx < 2 * NN) s += g_cnt[idx];
    }
    part[t] = s;
    __syncthreads();
    for (int off = 1; off < T; off <<= 1) {
        int v = (t >= off) ? part[t - off] : 0;
        __syncthreads();
        part[t] += v;
        __syncthreads();
    }
    int run = (t == 0) ? 0 : part[t - 1];
    for (int i = 0; i < CH; i++) {
        int idx = base + i;
        if (idx < 2 * NN) {
            g_off[idx] = run;
            g_cursor[idx] = run;
            run += g_cnt[idx];
        }
    }
    if (t == T - 1) g_off[2 * NN] = run;
}
__global__ void k_fill(const int* __restrict__ src, const int* __restrict__ dst,
                       const int* __restrict__ et) {
    int e = blockIdx.x * blockDim.x + threadIdx.x;
    if (e >= EE) return;
    int seg = et[e] * NN + dst[e];
    int pos = atomicAdd(&g_cursor[seg], 1);
    g_eidx[pos] = src[e];
}

// ---------------- fused gather-aggregate (one warp per node, fp16 messages) ---
// lane covers dims [lane*8, lane*8+8). FINAL=1: fused head logits.
template <int FINAL>
__global__ void __launch_bounds__(256) k_aggregate(int outSlot,
                                                   const float* __restrict__ Wout,
                                                   const float* __restrict__ bout,
                                                   float* __restrict__ out)
{
    int gw = (blockIdx.x * blockDim.x + threadIdx.x) >> 5;
    int lane = threadIdx.x & 31;
    if (gw >= NN) return;

    float a[8];
    {
        const float4* rootp = (const float4*)(g_hroot + (size_t)gw * HD + lane * 8);
        float4 r0 = rootp[0], r1 = rootp[1];
        a[0] = r0.x; a[1] = r0.y; a[2] = r0.z; a[3] = r0.w;
        a[4] = r1.x; a[5] = r1.y; a[6] = r1.z; a[7] = r1.w;
    }

#pragma unroll
    for (int rel = 0; rel < 2; rel++) {
        int s0 = g_off[rel * NN + gw];
        int s1 = g_off[rel * NN + gw + 1];
        float t[8];
#pragma unroll
        for (int q = 0; q < 8; q++) t[q] = 0.f;
        const __half* hb = g_hrel + (size_t)rel * NN * HD;
        int i = s0;
        for (; i + 1 < s1; i += 2) {
            int sn0 = g_eidx[i], sn1 = g_eidx[i + 1];
            uint4 w0 = *(const uint4*)(hb + (size_t)sn0 * HD + lane * 8);
            uint4 w1 = *(const uint4*)(hb + (size_t)sn1 * HD + lane * 8);
            const uint32_t* p0 = &w0.x;
            const uint32_t* p1 = &w1.x;
#pragma unroll
            for (int q = 0; q < 4; q++) {
                float2 f0 = __half22float2(*(const __half2*)&p0[q]);
                float2 f1 = __half22float2(*(const __half2*)&p1[q]);
                t[q * 2 + 0] += f0.x + f1.x;
                t[q * 2 + 1] += f0.y + f1.y;
            }
        }
        if (i < s1) {
            int sn = g_eidx[i];
            uint4 w0 = *(const uint4*)(hb + (size_t)sn * HD + lane * 8);
            const uint32_t* p0 = &w0.x;
#pragma unroll
            for (int q = 0; q < 4; q++) {
                float2 f0 = __half22float2(*(const __half2*)&p0[q]);
                t[q * 2 + 0] += f0.x;
                t[q * 2 + 1] += f0.y;
            }
        }
        int deg = s1 - s0;
        float inv = 1.f / (float)(deg > 0 ? deg : 1);
#pragma unroll
        for (int q = 0; q < 8; q++) a[q] += t[q] * inv;
    }

    if (FINAL == 0) {
        size_t eoff = (size_t)outSlot * NP * HD + (size_t)gw * HD + lane * 8;
        uint4 hv;
        *(__half2*)&hv.x = __floats2half2_rn(a[0], a[1]);
        *(__half2*)&hv.y = __floats2half2_rn(a[2], a[3]);
        *(__half2*)&hv.z = __floats2half2_rn(a[4], a[5]);
        *(__half2*)&hv.w = __floats2half2_rn(a[6], a[7]);
        *(uint4*)(g_x + eoff) = hv;
    } else {
        float s0 = 0.f, s1 = 0.f;
        int c0 = lane * 8;
#pragma unroll
        for (int q = 0; q < 8; q++) {
            float2 w = *(const float2*)(Wout + (c0 + q) * 2);
            s0 += a[q] * w.x;
            s1 += a[q] * w.y;
        }
#pragma unroll
        for (int o = 16; o; o >>= 1) {
            s0 += __shfl_down_sync(0xFFFFFFFFu, s0, o);
            s1 += __shfl_down_sync(0xFFFFFFFFu, s1, o);
        }
        if (lane == 0) {
            out[(size_t)gw * 2 + 0] = s0 + bout[0];
            out[(size_t)gw * 2 + 1] = s1 + bout[1];
        }
    }
}

// ---------------- launch ------------------------------------------------------
extern "C" void kernel_launch(void* const* d_in, const int* in_sizes, int n_in,
                              void* d_out, int out_size)
{
    const float* des   = (const float*)d_in[0];
    const float* tweet = (const float*)d_in[1];
    const float* nump  = (const float*)d_in[2];
    const float* catp  = (const float*)d_in[3];
    const int*   ei    = (const int*)d_in[4];
    const int*   et    = (const int*)d_in[5];
    const float* w_des = (const float*)d_in[6];
    const float* b_des = (const float*)d_in[7];
    const float* w_tw  = (const float*)d_in[8];
    const float* b_tw  = (const float*)d_in[9];
    const float* w_num = (const float*)d_in[10];
    const float* b_num = (const float*)d_in[11];
    const float* w_cat = (const float*)d_in[12];
    const float* b_cat = (const float*)d_in[13];
    const float* w_in  = (const float*)d_in[14];
    const float* b_in  = (const float*)d_in[15];
    const float* wt1   = (const float*)d_in[16];
    const float* rt1   = (const float*)d_in[17];
    const float* bs1   = (const float*)d_in[18];
    const float* wt2   = (const float*)d_in[19];
    const float* rt2   = (const float*)d_in[20];
    const float* bs2   = (const float*)d_in[21];
    const float* w_out = (const float*)d_in[22];
    const float* b_out = (const float*)d_in[23];
    float* out = (float*)d_out;

    const int* src = ei;
    const int* dst = ei + EE;

    const int SZ128 = 2 * 18432 + 2 * 128 * 144;    // 73728
    const int SZ64  = 2 * 18432 + 2 * 64 * 144;     // 55296
    cudaFuncSetAttribute(k_gemm_mma<128, 1>, cudaFuncAttributeMaxDynamicSharedMemorySize, SZ128);
    cudaFuncSetAttribute(k_gemm_mma<64, 0>,  cudaFuncAttributeMaxDynamicSharedMemorySize, SZ64);

    // weight prep: one launch for all 9 matrices (grid sized for largest, 256x256)
    k_wprep<<<dim3((256 * 256 + 255) / 256, 9), 256>>>(w_des, w_tw, w_in, wt1, rt1, wt2, rt2);

    // CSR build
    k_zero_cnt<<<(2 * NN + 255) / 256, 256>>>();
    k_count<<<(EE + 255) / 256, 256>>>(dst, et);
    k_scan<<<1, 1024>>>();
    k_fill<<<(EE + 255) / 256, 256>>>(src, dst, et);

    const int MB = (NN + 127) / 128;  // 391 row tiles

    // feature projections -> slot0 (des + tweet merged; num + cat merged)
    k_gemm_mma<64, 0><<<dim3(2, MB), 256, SZ64>>>(des, tweet, 0, 768, NN, 0,
                                                  b_des, b_tw, 1, 64, 0, 1);
    k_projsmall<<<dim3((NN * 64 + 255) / 256, 2), 256>>>(nump, w_num, b_num,
                                                         catp, w_cat, b_cat);

    // x = lrelu(slot0 @ w_in + b_in) -> slot1
    k_gemm_mma<128, 1><<<dim3(2, MB), 256, SZ128>>>(nullptr, nullptr, 0, 256, NN, OFF_WIN,
                                                    b_in, nullptr, 2, 0, 0, 1);

    const int agBl = (NN * 32 + 255) / 256;

    // RGCN layer 1: slot1 -> g_hrel/g_hroot -> slot0
    k_gemm_mma<128, 1><<<dim3(6, MB), 256, SZ128>>>(nullptr, nullptr, 1, 256, NN, OFF_R1,
                                                    bs1, nullptr, 3, 0, 1, 2);
    k_aggregate<0><<<agBl, 256>>>(0, nullptr, nullptr, nullptr);

    // RGCN layer 2: slot0 -> g_hrel/g_hroot -> head logits (fused)
    k_gemm_mma<128, 1><<<dim3(6, MB), 256, SZ128>>>(nullptr, nullptr, 0, 256, NN, OFF_R2,
                                                    bs2, nullptr, 3, 0, 1, 2);
    k_aggregate<1><<<agBl, 256>>>(0, w_out, b_out, out);
}

// round 15
// speedup vs baseline: 2.4152x; 1.2768x over previous
#include <cuda_runtime.h>
#include <cuda_bf16.h>
#include <cuda_fp16.h>
#include <cstdint>

#define NN 50000
#define NP 50048          // padded rows (multiple of 128) for unguarded cp.async
#define EE 800000
#define HD 256
#define DESW 768
#define NSEG (2 * NN)
#define SCAN_B ((NSEG + 1023) / 1024)   // 98 scan blocks

// ---------------- scratch (device globals; no runtime alloc) ----------------
__device__ __align__(16) __half g_x[(size_t)2 * NP * HD];      // fp16 activations, 2 slots
__device__ __align__(16) __half g_hrel[(size_t)2 * NN * HD];   // fp16 messages
__device__ __align__(16) float  g_hroot[(size_t)NN * HD];      // fp32 root
__device__ __align__(16) int   g_cnt[NSEG];
__device__ __align__(16) int   g_off[NSEG + 1];
__device__ __align__(16) int   g_cursor[NSEG];
__device__ __align__(16) int   g_eidx[EE];
__device__ __align__(16) int   g_bsum[128];
__device__ __align__(16) int   g_bpre[128];

#define OFF_DES 0
#define OFF_TW  49152
#define OFF_WIN 98304
#define OFF_R1  163840
#define OFF_R2  360448
__device__ __align__(16) __half g_w[557056];     // fp16 weights, transposed [N,K]

// ---------------- helpers -----------------------------------------------------
__device__ __forceinline__ uint32_t smem_u32(const void* p) {
    uint32_t a;
    asm("{ .reg .u64 t; cvta.to.shared.u64 t, %1; cvt.u32.u64 %0, t; }" : "=r"(a) : "l"(p));
    return a;
}
__device__ __forceinline__ void ldsm4(uint32_t* r, uint32_t addr) {
    asm volatile("ldmatrix.sync.aligned.m8n8.x4.shared.b16 {%0,%1,%2,%3}, [%4];"
                 : "=r"(r[0]), "=r"(r[1]), "=r"(r[2]), "=r"(r[3]) : "r"(addr));
}
__device__ __forceinline__ void mma_f16(float* c, const uint32_t* a, const uint32_t* b) {
    asm volatile(
        "mma.sync.aligned.m16n8k16.row.col.f32.f16.f16.f32 "
        "{%0,%1,%2,%3}, {%4,%5,%6,%7}, {%8,%9}, {%0,%1,%2,%3};"
        : "+f"(c[0]), "+f"(c[1]), "+f"(c[2]), "+f"(c[3])
        : "r"(a[0]), "r"(a[1]), "r"(a[2]), "r"(a[3]), "r"(b[0]), "r"(b[1]));
}
__device__ __forceinline__ void cpa16(uint32_t dst, const void* src) {
    asm volatile("cp.async.cg.shared.global [%0], [%1], 16;" :: "r"(dst), "l"(src));
}
__device__ __forceinline__ void cp_commit() {
    asm volatile("cp.async.commit_group;" ::: "memory");
}
template <int N>
__device__ __forceinline__ void cp_wait() {
    asm volatile("cp.async.wait_group %0;" :: "n"(N) : "memory");
}
__device__ __forceinline__ float actf(float v, int act) {
    if (act == 1) return v > 0.f ? v : 0.01f * v;
    if (act == 2) return v > 0.f ? v : 0.f;
    return v;
}
// 8 fp32 -> 8 fp16 packed in uint4
__device__ __forceinline__ uint4 cvt8h(float4 x, float4 y) {
    uint4 r;
    *(__half2*)&r.x = __floats2half2_rn(x.x, x.y);
    *(__half2*)&r.y = __floats2half2_rn(x.z, x.w);
    *(__half2*)&r.z = __floats2half2_rn(y.x, y.y);
    *(__half2*)&r.w = __floats2half2_rn(y.z, y.w);
    return r;
}

// ---------------- weight prep: all 9 matrices in ONE launch -------------------
__global__ void k_wprep(const float* __restrict__ w_des, const float* __restrict__ w_tw,
                        const float* __restrict__ w_in, const float* __restrict__ wt1,
                        const float* __restrict__ rt1, const float* __restrict__ wt2,
                        const float* __restrict__ rt2) {
    int id = blockIdx.x * blockDim.x + threadIdx.x;
    int y = blockIdx.y;
    const float* W;
    int off, K, N;
    switch (y) {
        case 0: W = w_des;         off = OFF_DES;           K = 768; N = 64;  break;
        case 1: W = w_tw;          off = OFF_TW;            K = 768; N = 64;  break;
        case 2: W = w_in;          off = OFF_WIN;           K = 256; N = 256; break;
        case 3: W = wt1;           off = OFF_R1;            K = 256; N = 256; break;
        case 4: W = wt1 + 65536;   off = OFF_R1 + 65536;    K = 256; N = 256; break;
        case 5: W = rt1;           off = OFF_R1 + 131072;   K = 256; N = 256; break;
        case 6: W = wt2;           off = OFF_R2;            K = 256; N = 256; break;
        case 7: W = wt2 + 65536;   off = OFF_R2 + 65536;    K = 256; N = 256; break;
        default: W = rt2;          off = OFF_R2 + 131072;   K = 256; N = 256; break;
    }
    if (id >= K * N) return;
    int k = id / N, n = id - k * N;
    g_w[(size_t)off + (size_t)n * K + k] = __float2half_rn(W[id]);
}

// ---------------- cp.async double-buffered pure-fp16 GEMM ---------------------
template <int BN, int AMODE>
__global__ void __launch_bounds__(256) k_gemm_mma(
    const float* __restrict__ Ap0, const float* __restrict__ Ap1, int aSlot,
    int K, int M, int bOff,
    const float* __restrict__ bias0, const float* __restrict__ bias1,
    int cSel, int cbase, int cmode, int act)
{
    extern __shared__ char sm[];
    constexpr int STR = 144;
    constexpr int ABUF = 128 * STR;
    constexpr int BBUF = BN * STR;
    constexpr int NT = BN / 16;

    const uint32_t smb = smem_u32(sm);
    const int tid = threadIdx.x;
    const int lane = tid & 31, wid = tid >> 5;
    const int m_base = (wid & 3) * 32;
    const int n_base = (wid >> 2) * (BN / 2);

    const float* Aparam = (AMODE == 0 && blockIdx.x) ? Ap1 : Ap0;
    const float* bias = (AMODE == 0 && blockIdx.x) ? bias1 : bias0;
    const int cb = (AMODE == 0) ? (blockIdx.x ? cbase : 0) : cbase;
    const int boff_g = (AMODE == 0) ? (blockIdx.x ? OFF_TW : OFF_DES) : bOff;

    const __half* Ah = g_x + (size_t)aSlot * NP * HD;
    const __half* B = g_w + boff_g;

    const int m0 = blockIdx.y * 128;
    const int n0 = (AMODE == 0) ? 0 : blockIdx.x * BN;
    const int nch = K >> 6;

    const int lrow = tid >> 1, lhalf = tid & 1;

    float acc[2][NT][4];
#pragma unroll
    for (int i = 0; i < 2; i++)
#pragma unroll
        for (int j = 0; j < NT; j++)
#pragma unroll
            for (int q = 0; q < 4; q++) acc[i][j][q] = 0.f;

    const uint32_t aoff = (uint32_t)(m_base + (lane & 15)) * STR + (uint32_t)(lane >> 4) * 16;
    const uint32_t boff = (uint32_t)(n_base + ((lane >> 4) & 1) * 8 + (lane & 7)) * STR +
                          (uint32_t)((lane >> 3) & 1) * 16;

    float4 areg[8];
    auto load_regs = [&](int c) {
        if (AMODE == 0) {
            int gr = m0 + lrow;
            if (gr < M) {
                const float4* srcp = (const float4*)(Aparam + (size_t)gr * K + c * 64 + lhalf * 32);
#pragma unroll
                for (int j = 0; j < 8; j++) areg[j] = srcp[j];
            } else {
#pragma unroll
                for (int j = 0; j < 8; j++) areg[j] = make_float4(0.f, 0.f, 0.f, 0.f);
            }
        }
    };

    auto loadA = [&](int c, int buf) {
        if (AMODE == 1) {
            int k0 = c * 64;
            size_t base = (size_t)(m0 + lrow) * HD + k0 + lhalf * 32;
            uint32_t d = smb + buf * ABUF + lrow * STR + lhalf * 64;
#pragma unroll
            for (int j = 0; j < 4; j++)
                cpa16(d + j * 16, Ah + base + j * 8);
        }
    };
    auto loadB = [&](int c, int buf) {
        if (lrow < BN) {
            int k0 = c * 64;
            size_t base = (size_t)(n0 + lrow) * K + k0 + lhalf * 32;
            uint32_t d = smb + 2 * ABUF + buf * BBUF + lrow * STR + lhalf * 64;
#pragma unroll
            for (int j = 0; j < 4; j++)
                cpa16(d + j * 16, B + base + j * 8);
        }
    };

    loadA(0, 0);
    loadB(0, 0);
    cp_commit();
    load_regs(0);

    for (int c = 0; c < nch; c++) {
        const int buf = c & 1;
        if (c + 1 < nch) {
            loadA(c + 1, buf ^ 1);
            loadB(c + 1, buf ^ 1);
            cp_commit();
            cp_wait<1>();
        } else {
            cp_wait<0>();
        }
        __syncthreads();

        if (AMODE == 0) {
            uint4 h[4];
#pragma unroll
            for (int j = 0; j < 4; j++) h[j] = cvt8h(areg[2 * j], areg[2 * j + 1]);
#pragma unroll
            for (int j = 0; j < 4; j++)
                *(uint4*)(sm + buf * ABUF + lrow * STR + lhalf * 64 + j * 16) = h[j];
            if (c + 1 < nch) load_regs(c + 1);
            __syncthreads();
        }

        const uint32_t ab = smb + buf * ABUF;
        const uint32_t bb = smb + 2 * ABUF + buf * BBUF;

#pragma unroll
        for (int k16 = 0; k16 < 4; k16++) {
            uint32_t aH[2][4];
#pragma unroll
            for (int mi = 0; mi < 2; mi++)
                ldsm4(aH[mi], ab + aoff + mi * (16 * STR) + k16 * 32);
#pragma unroll
            for (int pr = 0; pr < NT / 2; pr++) {
                uint32_t bH[4];
                ldsm4(bH, bb + boff + pr * (16 * STR) + k16 * 32);
#pragma unroll
                for (int mi = 0; mi < 2; mi++)
#pragma unroll
                    for (int t = 0; t < 2; t++)
                        mma_f16(acc[mi][pr * 2 + t], aH[mi], bH + 2 * t);
            }
        }
        __syncthreads();
    }

    // ---- epilogue ----
#pragma unroll
    for (int mi = 0; mi < 2; mi++) {
#pragma unroll
        for (int nt = 0; nt < NT; nt++) {
            int colL = n_base + nt * 8 + (lane & 3) * 2;
            int gcolL = n0 + colL;
            int bidx = (cmode == 1) ? (gcolL & 255) : colL;
            float b0 = bias[bidx], b1 = bias[bidx + 1];
#pragma unroll
            for (int half = 0; half < 2; half++) {
                int gr = m0 + m_base + mi * 16 + (lane >> 2) + half * 8;
                if (gr < M) {
                    float vx = actf(acc[mi][nt][half * 2 + 0] + b0, act);
                    float vy = actf(acc[mi][nt][half * 2 + 1] + b1, act);
                    __half2 hv = __floats2half2_rn(vx, vy);
                    if (cmode == 1) {
                        int seg = gcolL >> 8, lc = gcolL & 255;
                        if (seg < 2) {
                            *(__half2*)(g_hrel + ((size_t)seg * NN + gr) * 256 + lc) = hv;
                        } else {
                            *(float2*)(g_hroot + (size_t)gr * 256 + lc) = make_float2(vx, vy);
                        }
                    } else {
                        int slot = cSel - 1;
                        size_t eoff = (size_t)slot * NP * HD + (size_t)gr * HD + cb + gcolL;
                        *(__half2*)(g_x + eoff) = hv;
                    }
                }
            }
        }
    }
}

// ---------------- small projections (K=5 and K=3 merged) -> slot0 fp16 -------
__global__ void k_projsmall(const float* __restrict__ An, const float* __restrict__ Wn,
                            const float* __restrict__ bn,
                            const float* __restrict__ Ac, const float* __restrict__ Wc,
                            const float* __restrict__ bc)
{
    int id = blockIdx.x * blockDim.x + threadIdx.x;
    if (id >= NN * 64) return;
    int n = id >> 6, j = id & 63;
    const float* A = blockIdx.y ? Ac : An;
    const float* W = blockIdx.y ? Wc : Wn;
    const float* bias = blockIdx.y ? bc : bn;
    int K = blockIdx.y ? 3 : 5;
    int coloff = blockIdx.y ? 192 : 128;
    float s = bias[j];
    for (int k = 0; k < K; k++) s += A[(size_t)n * K + k] * W[k * 64 + j];
    s = actf(s, 1);
    g_x[(size_t)n * HD + coloff + j] = __float2half_rn(s);
}

// ---------------- CSR build ---------------------------------------------------
__global__ void k_zero_cnt() {
    int id = blockIdx.x * blockDim.x + threadIdx.x;
    if (id < NSEG) g_cnt[id] = 0;
}
__global__ void k_count(const int* __restrict__ dst, const int* __restrict__ et) {
    int e = blockIdx.x * blockDim.x + threadIdx.x;
    if (e >= EE) return;
    atomicAdd(&g_cnt[et[e] * NN + dst[e]], 1);
}
// parallel 3-pass exclusive scan over NSEG counts
__global__ void k_scan1() {          // grid SCAN_B x 1024
    __shared__ int sh[1024];
    int idx = blockIdx.x * 1024 + threadIdx.x;
    int v = (idx < NSEG) ? g_cnt[idx] : 0;
    sh[threadIdx.x] = v;
    __syncthreads();
    for (int off = 1; off < 1024; off <<= 1) {
        int t = (threadIdx.x >= off) ? sh[threadIdx.x - off] : 0;
        __syncthreads();
        sh[threadIdx.x] += t;
        __syncthreads();
    }
    if (idx < NSEG) g_off[idx] = sh[threadIdx.x] - v;   // within-block exclusive
    if (threadIdx.x == 1023) g_bsum[blockIdx.x] = sh[1023];
}
__global__ void k_scan2() {          // 1 block x 128
    __shared__ int sh[128];
    int v = (threadIdx.x < SCAN_B) ? g_bsum[threadIdx.x] : 0;
    sh[threadIdx.x] = v;
    __syncthreads();
    for (int off = 1; off < 128; off <<= 1) {
        int t = (threadIdx.x >= off) ? sh[threadIdx.x - off] : 0;
        __syncthreads();
        sh[threadIdx.x] += t;
        __syncthreads();
    }
    if (threadIdx.x < SCAN_B) g_bpre[threadIdx.x] = sh[threadIdx.x] - v;
    if (threadIdx.x == 127) g_off[NSEG] = sh[127];
}
__global__ void k_scan3() {          // grid SCAN_B x 1024
    int idx = blockIdx.x * 1024 + threadIdx.x;
    if (idx < NSEG) {
        int o = g_off[idx] + g_bpre[blockIdx.x];
        g_off[idx] = o;
        g_cursor[idx] = o;
    }
}
__global__ void k_fill(const int* __restrict__ src, const int* __restrict__ dst,
                       const int* __restrict__ et) {
    int e = blockIdx.x * blockDim.x + threadIdx.x;
    if (e >= EE) return;
    int seg = et[e] * NN + dst[e];
    int pos = atomicAdd(&g_cursor[seg], 1);
    g_eidx[pos] = src[e];
}

// ---------------- fused gather-aggregate (one warp per node, fp16 messages) ---
template <int FINAL>
__global__ void __launch_bounds__(256) k_aggregate(int outSlot,
                                                   const float* __restrict__ Wout,
                                                   const float* __restrict__ bout,
                                                   float* __restrict__ out)
{
    int gw = (blockIdx.x * blockDim.x + threadIdx.x) >> 5;
    int lane = threadIdx.x & 31;
    if (gw >= NN) return;

    float a[8];
    {
        const float4* rootp = (const float4*)(g_hroot + (size_t)gw * HD + lane * 8);
        float4 r0 = rootp[0], r1 = rootp[1];
        a[0] = r0.x; a[1] = r0.y; a[2] = r0.z; a[3] = r0.w;
        a[4] = r1.x; a[5] = r1.y; a[6] = r1.z; a[7] = r1.w;
    }

#pragma unroll
    for (int rel = 0; rel < 2; rel++) {
        int s0 = g_off[rel * NN + gw];
        int s1 = g_off[rel * NN + gw + 1];
        float t[8];
#pragma unroll
        for (int q = 0; q < 8; q++) t[q] = 0.f;
        const __half* hb = g_hrel + (size_t)rel * NN * HD;
        int i = s0;
        for (; i + 1 < s1; i += 2) {
            int sn0 = g_eidx[i], sn1 = g_eidx[i + 1];
            uint4 w0 = *(const uint4*)(hb + (size_t)sn0 * HD + lane * 8);
            uint4 w1 = *(const uint4*)(hb + (size_t)sn1 * HD + lane * 8);
            const uint32_t* p0 = &w0.x;
            const uint32_t* p1 = &w1.x;
#pragma unroll
            for (int q = 0; q < 4; q++) {
                float2 f0 = __half22float2(*(const __half2*)&p0[q]);
                float2 f1 = __half22float2(*(const __half2*)&p1[q]);
                t[q * 2 + 0] += f0.x + f1.x;
                t[q * 2 + 1] += f0.y + f1.y;
            }
        }
        if (i < s1) {
            int sn = g_eidx[i];
            uint4 w0 = *(const uint4*)(hb + (size_t)sn * HD + lane * 8);
            const uint32_t* p0 = &w0.x;
#pragma unroll
            for (int q = 0; q < 4; q++) {
                float2 f0 = __half22float2(*(const __half2*)&p0[q]);
                t[q * 2 + 0] += f0.x;
                t[q * 2 + 1] += f0.y;
            }
        }
        int deg = s1 - s0;
        float inv = 1.f / (float)(deg > 0 ? deg : 1);
#pragma unroll
        for (int q = 0; q < 8; q++) a[q] += t[q] * inv;
    }

    if (FINAL == 0) {
        size_t eoff = (size_t)outSlot * NP * HD + (size_t)gw * HD + lane * 8;
        uint4 hv;
        *(__half2*)&hv.x = __floats2half2_rn(a[0], a[1]);
        *(__half2*)&hv.y = __floats2half2_rn(a[2], a[3]);
        *(__half2*)&hv.z = __floats2half2_rn(a[4], a[5]);
        *(__half2*)&hv.w = __floats2half2_rn(a[6], a[7]);
        *(uint4*)(g_x + eoff) = hv;
    } else {
        float s0 = 0.f, s1 = 0.f;
        int c0 = lane * 8;
#pragma unroll
        for (int q = 0; q < 8; q++) {
            float2 w = *(const float2*)(Wout + (c0 + q) * 2);
            s0 += a[q] * w.x;
            s1 += a[q] * w.y;
        }
#pragma unroll
        for (int o = 16; o; o >>= 1) {
            s0 += __shfl_down_sync(0xFFFFFFFFu, s0, o);
            s1 += __shfl_down_sync(0xFFFFFFFFu, s1, o);
        }
        if (lane == 0) {
            out[(size_t)gw * 2 + 0] = s0 + bout[0];
            out[(size_t)gw * 2 + 1] = s1 + bout[1];
        }
    }
}

// ---------------- launch ------------------------------------------------------
extern "C" void kernel_launch(void* const* d_in, const int* in_sizes, int n_in,
                              void* d_out, int out_size)
{
    const float* des   = (const float*)d_in[0];
    const float* tweet = (const float*)d_in[1];
    const float* nump  = (const float*)d_in[2];
    const float* catp  = (const float*)d_in[3];
    const int*   ei    = (const int*)d_in[4];
    const int*   et    = (const int*)d_in[5];
    const float* w_des = (const float*)d_in[6];
    const float* b_des = (const float*)d_in[7];
    const float* w_tw  = (const float*)d_in[8];
    const float* b_tw  = (const float*)d_in[9];
    const float* w_num = (const float*)d_in[10];
    const float* b_num = (const float*)d_in[11];
    const float* w_cat = (const float*)d_in[12];
    const float* b_cat = (const float*)d_in[13];
    const float* w_in  = (const float*)d_in[14];
    const float* b_in  = (const float*)d_in[15];
    const float* wt1   = (const float*)d_in[16];
    const float* rt1   = (const float*)d_in[17];
    const float* bs1   = (const float*)d_in[18];
    const float* wt2   = (const float*)d_in[19];
    const float* rt2   = (const float*)d_in[20];
    const float* bs2   = (const float*)d_in[21];
    const float* w_out = (const float*)d_in[22];
    const float* b_out = (const float*)d_in[23];
    float* out = (float*)d_out;

    const int* src = ei;
    const int* dst = ei + EE;

    const int SZ128 = 2 * 18432 + 2 * 128 * 144;    // 73728
    const int SZ64  = 2 * 18432 + 2 * 64 * 144;     // 55296
    cudaFuncSetAttribute(k_gemm_mma<128, 1>, cudaFuncAttributeMaxDynamicSharedMemorySize, SZ128);
    cudaFuncSetAttribute(k_gemm_mma<64, 0>,  cudaFuncAttributeMaxDynamicSharedMemorySize, SZ64);

    // weight prep: one launch for all 9 matrices
    k_wprep<<<dim3((256 * 256 + 255) / 256, 9), 256>>>(w_des, w_tw, w_in, wt1, rt1, wt2, rt2);

    // CSR build (parallel scan)
    k_zero_cnt<<<(NSEG + 255) / 256, 256>>>();
    k_count<<<(EE + 255) / 256, 256>>>(dst, et);
    k_scan1<<<SCAN_B, 1024>>>();
    k_scan2<<<1, 128>>>();
    k_scan3<<<SCAN_B, 1024>>>();
    k_fill<<<(EE + 255) / 256, 256>>>(src, dst, et);

    const int MB = (NN + 127) / 128;  // 391 row tiles

    // feature projections -> slot0 (des + tweet merged; num + cat merged)
    k_gemm_mma<64, 0><<<dim3(2, MB), 256, SZ64>>>(des, tweet, 0, 768, NN, 0,
                                                  b_des, b_tw, 1, 64, 0, 1);
    k_projsmall<<<dim3((NN * 64 + 255) / 256, 2), 256>>>(nump, w_num, b_num,
                                                         catp, w_cat, b_cat);

    // x = lrelu(slot0 @ w_in + b_in) -> slot1
    k_gemm_mma<128, 1><<<dim3(2, MB), 256, SZ128>>>(nullptr, nullptr, 0, 256, NN, OFF_WIN,
                                                    b_in, nullptr, 2, 0, 0, 1);

    const int agBl = (NN * 32 + 255) / 256;

    // RGCN layer 1: slot1 -> g_hrel/g_hroot -> slot0
    k_gemm_mma<128, 1><<<dim3(6, MB), 256, SZ128>>>(nullptr, nullptr, 1, 256, NN, OFF_R1,
                                                    bs1, nullptr, 3, 0, 1, 2);
    k_aggregate<0><<<agBl, 256>>>(0, nullptr, nullptr, nullptr);

    // RGCN layer 2: slot0 -> g_hrel/g_hroot -> head logits (fused)
    k_gemm_mma<128, 1><<<dim3(6, MB), 256, SZ128>>>(nullptr, nullptr, 0, 256, NN, OFF_R2,
                                                    bs2, nullptr, 3, 0, 1, 2);
    k_aggregate<1><<<agBl, 256>>>(0, w_out, b_out, out);
}

// round 16
// speedup vs baseline: 2.5310x; 1.0480x over previous
#include <cuda_runtime.h>
#include <cuda_bf16.h>
#include <cuda_fp16.h>
#include <cstdint>

#define NN 50000
#define NP 50048          // padded rows (multiple of 128) for unguarded cp.async
#define EE 800000
#define HD 256
#define DESW 768
#define NSEG (2 * NN)
#define SCAN_B ((NSEG + 1023) / 1024)   // 98 scan blocks

// ---------------- scratch (device globals; no runtime alloc) ----------------
__device__ __align__(16) __half g_x[(size_t)2 * NP * HD];      // fp16 activations, 2 slots
__device__ __align__(16) __half g_hrel[(size_t)2 * NN * HD];   // fp16 messages
__device__ __align__(16) __half g_hroot[(size_t)NN * HD];      // fp16 root
__device__ __align__(16) int   g_cnt[NSEG];
__device__ __align__(16) int   g_off[NSEG + 1];
__device__ __align__(16) int   g_cursor[NSEG];
__device__ __align__(16) int   g_eidx[EE];
__device__ __align__(16) int   g_bsum[128];
__device__ __align__(16) int   g_bpre[128];

#define OFF_DES 0
#define OFF_TW  49152
#define OFF_WIN 98304
#define OFF_R1  163840
#define OFF_R2  360448
__device__ __align__(16) __half g_w[557056];     // fp16 weights, transposed [N,K]

// ---------------- helpers -----------------------------------------------------
__device__ __forceinline__ uint32_t smem_u32(const void* p) {
    uint32_t a;
    asm("{ .reg .u64 t; cvta.to.shared.u64 t, %1; cvt.u32.u64 %0, t; }" : "=r"(a) : "l"(p));
    return a;
}
__device__ __forceinline__ void ldsm4(uint32_t* r, uint32_t addr) {
    asm volatile("ldmatrix.sync.aligned.m8n8.x4.shared.b16 {%0,%1,%2,%3}, [%4];"
                 : "=r"(r[0]), "=r"(r[1]), "=r"(r[2]), "=r"(r[3]) : "r"(addr));
}
__device__ __forceinline__ void mma_f16(float* c, const uint32_t* a, const uint32_t* b) {
    asm volatile(
        "mma.sync.aligned.m16n8k16.row.col.f32.f16.f16.f32 "
        "{%0,%1,%2,%3}, {%4,%5,%6,%7}, {%8,%9}, {%0,%1,%2,%3};"
        : "+f"(c[0]), "+f"(c[1]), "+f"(c[2]), "+f"(c[3])
        : "r"(a[0]), "r"(a[1]), "r"(a[2]), "r"(a[3]), "r"(b[0]), "r"(b[1]));
}
__device__ __forceinline__ void cpa16(uint32_t dst, const void* src) {
    asm volatile("cp.async.cg.shared.global [%0], [%1], 16;" :: "r"(dst), "l"(src));
}
__device__ __forceinline__ void cp_commit() {
    asm volatile("cp.async.commit_group;" ::: "memory");
}
template <int N>
__device__ __forceinline__ void cp_wait() {
    asm volatile("cp.async.wait_group %0;" :: "n"(N) : "memory");
}
__device__ __forceinline__ float actf(float v, int act) {
    if (act == 1) return v > 0.f ? v : 0.01f * v;
    if (act == 2) return v > 0.f ? v : 0.f;
    return v;
}
// 8 fp32 -> 8 fp16 packed in uint4
__device__ __forceinline__ uint4 cvt8h(float4 x, float4 y) {
    uint4 r;
    *(__half2*)&r.x = __floats2half2_rn(x.x, x.y);
    *(__half2*)&r.y = __floats2half2_rn(x.z, x.w);
    *(__half2*)&r.z = __floats2half2_rn(y.x, y.y);
    *(__half2*)&r.w = __floats2half2_rn(y.z, y.w);
    return r;
}

// ---------------- weight prep: all 9 matrices in ONE launch -------------------
__global__ void k_wprep(const float* __restrict__ w_des, const float* __restrict__ w_tw,
                        const float* __restrict__ w_in, const float* __restrict__ wt1,
                        const float* __restrict__ rt1, const float* __restrict__ wt2,
                        const float* __restrict__ rt2) {
    int id = blockIdx.x * blockDim.x + threadIdx.x;
    int y = blockIdx.y;
    const float* W;
    int off, K, N;
    switch (y) {
        case 0: W = w_des;         off = OFF_DES;           K = 768; N = 64;  break;
        case 1: W = w_tw;          off = OFF_TW;            K = 768; N = 64;  break;
        case 2: W = w_in;          off = OFF_WIN;           K = 256; N = 256; break;
        case 3: W = wt1;           off = OFF_R1;            K = 256; N = 256; break;
        case 4: W = wt1 + 65536;   off = OFF_R1 + 65536;    K = 256; N = 256; break;
        case 5: W = rt1;           off = OFF_R1 + 131072;   K = 256; N = 256; break;
        case 6: W = wt2;           off = OFF_R2;            K = 256; N = 256; break;
        case 7: W = wt2 + 65536;   off = OFF_R2 + 65536;    K = 256; N = 256; break;
        default: W = rt2;          off = OFF_R2 + 131072;   K = 256; N = 256; break;
    }
    if (id >= K * N) return;
    int k = id / N, n = id - k * N;
    g_w[(size_t)off + (size_t)n * K + k] = __float2half_rn(W[id]);
}

// ---------------- cp.async double-buffered pure-fp16 GEMM ---------------------
template <int BN, int AMODE>
__global__ void __launch_bounds__(256) k_gemm_mma(
    const float* __restrict__ Ap0, const float* __restrict__ Ap1, int aSlot,
    int K, int M, int bOff,
    const float* __restrict__ bias0, const float* __restrict__ bias1,
    int cSel, int cbase, int cmode, int act)
{
    extern __shared__ char sm[];
    constexpr int STR = 144;
    constexpr int ABUF = 128 * STR;
    constexpr int BBUF = BN * STR;
    constexpr int NT = BN / 16;

    const uint32_t smb = smem_u32(sm);
    const int tid = threadIdx.x;
    const int lane = tid & 31, wid = tid >> 5;
    const int m_base = (wid & 3) * 32;
    const int n_base = (wid >> 2) * (BN / 2);

    const float* Aparam = (AMODE == 0 && blockIdx.x) ? Ap1 : Ap0;
    const float* bias = (AMODE == 0 && blockIdx.x) ? bias1 : bias0;
    const int cb = (AMODE == 0) ? (blockIdx.x ? cbase : 0) : cbase;
    const int boff_g = (AMODE == 0) ? (blockIdx.x ? OFF_TW : OFF_DES) : bOff;

    const __half* Ah = g_x + (size_t)aSlot * NP * HD;
    const __half* B = g_w + boff_g;

    const int m0 = blockIdx.y * 128;
    const int n0 = (AMODE == 0) ? 0 : blockIdx.x * BN;
    const int nch = K >> 6;

    const int lrow = tid >> 1, lhalf = tid & 1;

    float acc[2][NT][4];
#pragma unroll
    for (int i = 0; i < 2; i++)
#pragma unroll
        for (int j = 0; j < NT; j++)
#pragma unroll
            for (int q = 0; q < 4; q++) acc[i][j][q] = 0.f;

    const uint32_t aoff = (uint32_t)(m_base + (lane & 15)) * STR + (uint32_t)(lane >> 4) * 16;
    const uint32_t boff = (uint32_t)(n_base + ((lane >> 4) & 1) * 8 + (lane & 7)) * STR +
                          (uint32_t)((lane >> 3) & 1) * 16;

    float4 areg[8];
    auto load_regs = [&](int c) {
        if (AMODE == 0) {
            int gr = m0 + lrow;
            if (gr < M) {
                const float4* srcp = (const float4*)(Aparam + (size_t)gr * K + c * 64 + lhalf * 32);
#pragma unroll
                for (int j = 0; j < 8; j++) areg[j] = srcp[j];
            } else {
#pragma unroll
                for (int j = 0; j < 8; j++) areg[j] = make_float4(0.f, 0.f, 0.f, 0.f);
            }
        }
    };

    auto loadA = [&](int c, int buf) {
        if (AMODE == 1) {
            int k0 = c * 64;
            size_t base = (size_t)(m0 + lrow) * HD + k0 + lhalf * 32;
            uint32_t d = smb + buf * ABUF + lrow * STR + lhalf * 64;
#pragma unroll
            for (int j = 0; j < 4; j++)
                cpa16(d + j * 16, Ah + base + j * 8);
        }
    };
    auto loadB = [&](int c, int buf) {
        if (lrow < BN) {
            int k0 = c * 64;
            size_t base = (size_t)(n0 + lrow) * K + k0 + lhalf * 32;
            uint32_t d = smb + 2 * ABUF + buf * BBUF + lrow * STR + lhalf * 64;
#pragma unroll
            for (int j = 0; j < 4; j++)
                cpa16(d + j * 16, B + base + j * 8);
        }
    };

    loadA(0, 0);
    loadB(0, 0);
    cp_commit();
    load_regs(0);

    for (int c = 0; c < nch; c++) {
        const int buf = c & 1;
        if (c + 1 < nch) {
            loadA(c + 1, buf ^ 1);
            loadB(c + 1, buf ^ 1);
            cp_commit();
            cp_wait<1>();
        } else {
            cp_wait<0>();
        }
        __syncthreads();

        if (AMODE == 0) {
            uint4 h[4];
#pragma unroll
            for (int j = 0; j < 4; j++) h[j] = cvt8h(areg[2 * j], areg[2 * j + 1]);
#pragma unroll
            for (int j = 0; j < 4; j++)
                *(uint4*)(sm + buf * ABUF + lrow * STR + lhalf * 64 + j * 16) = h[j];
            if (c + 1 < nch) load_regs(c + 1);
            __syncthreads();
        }

        const uint32_t ab = smb + buf * ABUF;
        const uint32_t bb = smb + 2 * ABUF + buf * BBUF;

#pragma unroll
        for (int k16 = 0; k16 < 4; k16++) {
            uint32_t aH[2][4];
#pragma unroll
            for (int mi = 0; mi < 2; mi++)
                ldsm4(aH[mi], ab + aoff + mi * (16 * STR) + k16 * 32);
#pragma unroll
            for (int pr = 0; pr < NT / 2; pr++) {
                uint32_t bH[4];
                ldsm4(bH, bb + boff + pr * (16 * STR) + k16 * 32);
#pragma unroll
                for (int mi = 0; mi < 2; mi++)
#pragma unroll
                    for (int t = 0; t < 2; t++)
                        mma_f16(acc[mi][pr * 2 + t], aH[mi], bH + 2 * t);
            }
        }
        __syncthreads();
    }

    // ---- epilogue ----
#pragma unroll
    for (int mi = 0; mi < 2; mi++) {
#pragma unroll
        for (int nt = 0; nt < NT; nt++) {
            int colL = n_base + nt * 8 + (lane & 3) * 2;
            int gcolL = n0 + colL;
            int bidx = (cmode == 1) ? (gcolL & 255) : colL;
            float b0 = bias[bidx], b1 = bias[bidx + 1];
#pragma unroll
            for (int half = 0; half < 2; half++) {
                int gr = m0 + m_base + mi * 16 + (lane >> 2) + half * 8;
                if (gr < M) {
                    float vx = actf(acc[mi][nt][half * 2 + 0] + b0, act);
                    float vy = actf(acc[mi][nt][half * 2 + 1] + b1, act);
                    __half2 hv = __floats2half2_rn(vx, vy);
                    if (cmode == 1) {
                        int seg = gcolL >> 8, lc = gcolL & 255;
                        __half* dstp = (seg < 2)
                            ? g_hrel + ((size_t)seg * NN + gr) * 256 + lc
                            : g_hroot + (size_t)gr * 256 + lc;
                        *(__half2*)dstp = hv;
                    } else {
                        int slot = cSel - 1;
                        size_t eoff = (size_t)slot * NP * HD + (size_t)gr * HD + cb + gcolL;
                        *(__half2*)(g_x + eoff) = hv;
                    }
                }
            }
        }
    }
}

// ---------------- small projections (K=5 and K=3 merged) -> slot0 fp16 -------
__global__ void k_projsmall(const float* __restrict__ An, const float* __restrict__ Wn,
                            const float* __restrict__ bn,
                            const float* __restrict__ Ac, const float* __restrict__ Wc,
                            const float* __restrict__ bc)
{
    int id = blockIdx.x * blockDim.x + threadIdx.x;
    if (id >= NN * 64) return;
    int n = id >> 6, j = id & 63;
    const float* A = blockIdx.y ? Ac : An;
    const float* W = blockIdx.y ? Wc : Wn;
    const float* bias = blockIdx.y ? bc : bn;
    int K = blockIdx.y ? 3 : 5;
    int coloff = blockIdx.y ? 192 : 128;
    float s = bias[j];
    for (int k = 0; k < K; k++) s += A[(size_t)n * K + k] * W[k * 64 + j];
    s = actf(s, 1);
    g_x[(size_t)n * HD + coloff + j] = __float2half_rn(s);
}

// ---------------- CSR build ---------------------------------------------------
__global__ void k_zero_cnt() {
    int id = blockIdx.x * blockDim.x + threadIdx.x;
    if (id < NSEG) g_cnt[id] = 0;
}
__global__ void k_count(const int* __restrict__ dst, const int* __restrict__ et) {
    int e = blockIdx.x * blockDim.x + threadIdx.x;
    if (e >= EE) return;
    atomicAdd(&g_cnt[et[e] * NN + dst[e]], 1);
}
__global__ void k_scan1() {
    __shared__ int sh[1024];
    int idx = blockIdx.x * 1024 + threadIdx.x;
    int v = (idx < NSEG) ? g_cnt[idx] : 0;
    sh[threadIdx.x] = v;
    __syncthreads();
    for (int off = 1; off < 1024; off <<= 1) {
        int t = (threadIdx.x >= off) ? sh[threadIdx.x - off] : 0;
        __syncthreads();
        sh[threadIdx.x] += t;
        __syncthreads();
    }
    if (idx < NSEG) g_off[idx] = sh[threadIdx.x] - v;
    if (threadIdx.x == 1023) g_bsum[blockIdx.x] = sh[1023];
}
__global__ void k_scan2() {
    __shared__ int sh[128];
    int v = (threadIdx.x < SCAN_B) ? g_bsum[threadIdx.x] : 0;
    sh[threadIdx.x] = v;
    __syncthreads();
    for (int off = 1; off < 128; off <<= 1) {
        int t = (threadIdx.x >= off) ? sh[threadIdx.x - off] : 0;
        __syncthreads();
        sh[threadIdx.x] += t;
        __syncthreads();
    }
    if (threadIdx.x < SCAN_B) g_bpre[threadIdx.x] = sh[threadIdx.x] - v;
    if (threadIdx.x == 127) g_off[NSEG] = sh[127];
}
__global__ void k_scan3() {
    int idx = blockIdx.x * 1024 + threadIdx.x;
    if (idx < NSEG) {
        int o = g_off[idx] + g_bpre[blockIdx.x];
        g_off[idx] = o;
        g_cursor[idx] = o;
    }
}
__global__ void k_fill(const int* __restrict__ src, const int* __restrict__ dst,
                       const int* __restrict__ et) {
    int e = blockIdx.x * blockDim.x + threadIdx.x;
    if (e >= EE) return;
    int seg = et[e] * NN + dst[e];
    int pos = atomicAdd(&g_cursor[seg], 1);
    g_eidx[pos] = src[e];
}

// ---------------- fused gather-aggregate (one warp per node, fp16 h) ----------
template <int FINAL>
__global__ void __launch_bounds__(256) k_aggregate(int outSlot,
                                                   const float* __restrict__ Wout,
                                                   const float* __restrict__ bout,
                                                   float* __restrict__ out)
{
    int gw = (blockIdx.x * blockDim.x + threadIdx.x) >> 5;
    int lane = threadIdx.x & 31;
    if (gw >= NN) return;

    float a[8];
    {
        uint4 w0 = *(const uint4*)(g_hroot + (size_t)gw * HD + lane * 8);
        const uint32_t* p0 = &w0.x;
#pragma unroll
        for (int q = 0; q < 4; q++) {
            float2 f0 = __half22float2(*(const __half2*)&p0[q]);
            a[q * 2 + 0] = f0.x;
            a[q * 2 + 1] = f0.y;
        }
    }

#pragma unroll
    for (int rel = 0; rel < 2; rel++) {
        int s0 = g_off[rel * NN + gw];
        int s1 = g_off[rel * NN + gw + 1];
        float t[8];
#pragma unroll
        for (int q = 0; q < 8; q++) t[q] = 0.f;
        const __half* hb = g_hrel + (size_t)rel * NN * HD;
        int i = s0;
        for (; i + 1 < s1; i += 2) {
            int sn0 = g_eidx[i], sn1 = g_eidx[i + 1];
            uint4 w0 = *(const uint4*)(hb + (size_t)sn0 * HD + lane * 8);
            uint4 w1 = *(const uint4*)(hb + (size_t)sn1 * HD + lane * 8);
            const uint32_t* p0 = &w0.x;
            const uint32_t* p1 = &w1.x;
#pragma unroll
            for (int q = 0; q < 4; q++) {
                float2 f0 = __half22float2(*(const __half2*)&p0[q]);
                float2 f1 = __half22float2(*(const __half2*)&p1[q]);
                t[q * 2 + 0] += f0.x + f1.x;
                t[q * 2 + 1] += f0.y + f1.y;
            }
        }
        if (i < s1) {
            int sn = g_eidx[i];
            uint4 w0 = *(const uint4*)(hb + (size_t)sn * HD + lane * 8);
            const uint32_t* p0 = &w0.x;
#pragma unroll
            for (int q = 0; q < 4; q++) {
                float2 f0 = __half22float2(*(const __half2*)&p0[q]);
                t[q * 2 + 0] += f0.x;
                t[q * 2 + 1] += f0.y;
            }
        }
        int deg = s1 - s0;
        float inv = 1.f / (float)(deg > 0 ? deg : 1);
#pragma unroll
        for (int q = 0; q < 8; q++) a[q] += t[q] * inv;
    }

    if (FINAL == 0) {
        size_t eoff = (size_t)outSlot * NP * HD + (size_t)gw * HD + lane * 8;
        uint4 hv;
        *(__half2*)&hv.x = __floats2half2_rn(a[0], a[1]);
        *(__half2*)&hv.y = __floats2half2_rn(a[2], a[3]);
        *(__half2*)&hv.z = __floats2half2_rn(a[4], a[5]);
        *(__half2*)&hv.w = __floats2half2_rn(a[6], a[7]);
        *(uint4*)(g_x + eoff) = hv;
    } else {
        float s0 = 0.f, s1 = 0.f;
        int c0 = lane * 8;
#pragma unroll
        for (int q = 0; q < 8; q++) {
            float2 w = *(const float2*)(Wout + (c0 + q) * 2);
            s0 += a[q] * w.x;
            s1 += a[q] * w.y;
        }
#pragma unroll
        for (int o = 16; o; o >>= 1) {
            s0 += __shfl_down_sync(0xFFFFFFFFu, s0, o);
            s1 += __shfl_down_sync(0xFFFFFFFFu, s1, o);
        }
        if (lane == 0) {
            out[(size_t)gw * 2 + 0] = s0 + bout[0];
            out[(size_t)gw * 2 + 1] = s1 + bout[1];
        }
    }
}

// ---------------- launch ------------------------------------------------------
extern "C" void kernel_launch(void* const* d_in, const int* in_sizes, int n_in,
                              void* d_out, int out_size)
{
    const float* des   = (const float*)d_in[0];
    const float* tweet = (const float*)d_in[1];
    const float* nump  = (const float*)d_in[2];
    const float* catp  = (const float*)d_in[3];
    const int*   ei    = (const int*)d_in[4];
    const int*   et    = (const int*)d_in[5];
    const float* w_des = (const float*)d_in[6];
    const float* b_des = (const float*)d_in[7];
    const float* w_tw  = (const float*)d_in[8];
    const float* b_tw  = (const float*)d_in[9];
    const float* w_num = (const float*)d_in[10];
    const float* b_num = (const float*)d_in[11];
    const float* w_cat = (const float*)d_in[12];
    const float* b_cat = (const float*)d_in[13];
    const float* w_in  = (const float*)d_in[14];
    const float* b_in  = (const float*)d_in[15];
    const float* wt1   = (const float*)d_in[16];
    const float* rt1   = (const float*)d_in[17];
    const float* bs1   = (const float*)d_in[18];
    const float* wt2   = (const float*)d_in[19];
    const float* rt2   = (const float*)d_in[20];
    const float* bs2   = (const float*)d_in[21];
    const float* w_out = (const float*)d_in[22];
    const float* b_out = (const float*)d_in[23];
    float* out = (float*)d_out;

    const int* src = ei;
    const int* dst = ei + EE;

    const int SZ128 = 2 * 18432 + 2 * 128 * 144;    // 73728
    const int SZ64  = 2 * 18432 + 2 * 64 * 144;     // 55296
    cudaFuncSetAttribute(k_gemm_mma<128, 1>, cudaFuncAttributeMaxDynamicSharedMemorySize, SZ128);
    cudaFuncSetAttribute(k_gemm_mma<64, 0>,  cudaFuncAttributeMaxDynamicSharedMemorySize, SZ64);

    // side stream for the independent CSR chain (captured via event fork/join)
    cudaStream_t cs;
    cudaStreamCreateWithFlags(&cs, cudaStreamNonBlocking);
    cudaEvent_t evFork, evJoin;
    cudaEventCreateWithFlags(&evFork, cudaEventDisableTiming);
    cudaEventCreateWithFlags(&evJoin, cudaEventDisableTiming);

    // fork: CSR build runs concurrently with weight prep + projections + GEMMs
    cudaEventRecord(evFork, 0);
    cudaStreamWaitEvent(cs, evFork, 0);
    k_zero_cnt<<<(NSEG + 255) / 256, 256, 0, cs>>>();
    k_count<<<(EE + 255) / 256, 256, 0, cs>>>(dst, et);
    k_scan1<<<SCAN_B, 1024, 0, cs>>>();
    k_scan2<<<1, 128, 0, cs>>>();
    k_scan3<<<SCAN_B, 1024, 0, cs>>>();
    k_fill<<<(EE + 255) / 256, 256, 0, cs>>>(src, dst, et);
    cudaEventRecord(evJoin, cs);

    // main chain on the capture-origin stream
    k_wprep<<<dim3((256 * 256 + 255) / 256, 9), 256>>>(w_des, w_tw, w_in, wt1, rt1, wt2, rt2);

    const int MB = (NN + 127) / 128;  // 391 row tiles

    k_gemm_mma<64, 0><<<dim3(2, MB), 256, SZ64>>>(des, tweet, 0, 768, NN, 0,
                                                  b_des, b_tw, 1, 64, 0, 1);
    k_projsmall<<<dim3((NN * 64 + 255) / 256, 2), 256>>>(nump, w_num, b_num,
                                                         catp, w_cat, b_cat);

    // x = lrelu(slot0 @ w_in + b_in) -> slot1
    k_gemm_mma<128, 1><<<dim3(2, MB), 256, SZ128>>>(nullptr, nullptr, 0, 256, NN, OFF_WIN,
                                                    b_in, nullptr, 2, 0, 0, 1);

    const int agBl = (NN * 32 + 255) / 256;

    // RGCN layer 1: slot1 -> g_hrel/g_hroot -> slot0
    k_gemm_mma<128, 1><<<dim3(6, MB), 256, SZ128>>>(nullptr, nullptr, 1, 256, NN, OFF_R1,
                                                    bs1, nullptr, 3, 0, 1, 2);
    cudaStreamWaitEvent(0, evJoin, 0);   // CSR must be ready before aggregation
    k_aggregate<0><<<agBl, 256>>>(0, nullptr, nullptr, nullptr);

    // RGCN layer 2: slot0 -> g_hrel/g_hroot -> head logits (fused)
    k_gemm_mma<128, 1><<<dim3(6, MB), 256, SZ128>>>(nullptr, nullptr, 0, 256, NN, OFF_R2,
                                                    bs2, nullptr, 3, 0, 1, 2);
    k_aggregate<1><<<agBl, 256>>>(0, w_out, b_out, out);

    cudaEventDestroy(evFork);
    cudaEventDestroy(evJoin);
    cudaStreamDestroy(cs);
}